// round 1
// baseline (speedup 1.0000x reference)
#include <cuda_runtime.h>
#include <math.h>

#define BB 64
#define SQ 320
#define NCV 256
#define DM 256
#define HIDN 1024
#define NHEADS 8
#define DHD 32
#define NDEPTH 6
#define WSQ 1089

// ---------------- device scratch (no allocations allowed) ----------------
__device__ float g_x[(size_t)BB * SQ * DM];
__device__ float g_ln[(size_t)BB * SQ * DM];
__device__ float g_qkv[(size_t)BB * SQ * 3 * DM];
__device__ float g_attn[(size_t)BB * SQ * DM];
__device__ float g_h1[(size_t)BB * SQ * HIDN];
__device__ float g_hcv[(size_t)BB * NCV * DM];
__device__ float g_cat[(size_t)BB * NCV * 2 * DM];
__device__ float g_patch[(size_t)BB * 64 * 768];

// ---------------- helpers ----------------
__device__ __forceinline__ float pos2d_val(int yy, int xx, int d) {
    int dd = d & 127;
    int i = dd >> 1;
    // exp(2i * -log(10000)/128)
    float freq = expf((float)(2 * i) * (-0.07195578415606394f));
    float coord = (d < 128) ? (float)yy : (float)xx;
    float ang = coord * freq;
    return (d & 1) ? cosf(ang) : sinf(ang);
}

__device__ __forceinline__ float gelu_exact(float v) {
    return 0.5f * v * (1.0f + erff(v * 0.70710678118654752f));
}

// ---------------- embed: gather cv tokens + pos ----------------
__global__ void __launch_bounds__(256) embed_k(const float* __restrict__ h_map,
                                               const int* __restrict__ idx,
                                               float* __restrict__ hcv,
                                               float* __restrict__ x) {
    int gid = blockIdx.x * 256 + threadIdx.x;   // < 64*256*256
    int d = gid & 255;
    int n = (gid >> 8) & 255;
    int b = gid >> 16;
    int p = idx[n];
    float h = h_map[((size_t)b * WSQ + p) * DM + d];
    hcv[gid] = h;
    x[((size_t)(b * SQ + n)) * DM + d] = h + pos2d_val(p / 33, p % 33, d);
}

// ---------------- im2col for patch embedding ----------------
__global__ void __launch_bounds__(256) im2col_k(const float* __restrict__ frame,
                                                float* __restrict__ patches) {
    int gid = blockIdx.x * 256 + threadIdx.x;   // < 4096*768
    int k = gid % 768;
    int m = gid / 768;
    int c = k >> 8;
    int r = (k >> 4) & 15;
    int q = k & 15;
    int t = m & 63, b = m >> 6;
    int yy = (t >> 3) * 16 + r;
    int xx = (t & 7) * 16 + q;
    patches[gid] = frame[(((size_t)b * 3 + c) * 128 + yy) * 128 + xx];
}

// ---------------- concat [hcv | ln_cv] for gate GEMM ----------------
__global__ void __launch_bounds__(256) cat_k(const float* __restrict__ hcv,
                                             const float* __restrict__ lnx,
                                             float* __restrict__ cat) {
    int gid = blockIdx.x * 256 + threadIdx.x;   // < 16384*512
    int dcol = gid & 511;
    int m = gid >> 9;
    int b = m >> 8, n = m & 255;
    cat[gid] = (dcol < 256) ? hcv[((size_t)m << 8) + dcol]
                            : lnx[(((size_t)(b * SQ + n)) << 8) + (dcol - 256)];
}

// ---------------- LayerNorm: one warp per token (D=256) ----------------
__global__ void __launch_bounds__(256) ln_k(const float* __restrict__ x,
                                            float* __restrict__ y,
                                            const float* __restrict__ gam,
                                            const float* __restrict__ bet) {
    int warp = threadIdx.x >> 5;
    int lane = threadIdx.x & 31;
    int tok = blockIdx.x * 8 + warp;
    const float* xp = x + (size_t)tok * DM;
    float v[8];
    float sum = 0.f, sq = 0.f;
#pragma unroll
    for (int i = 0; i < 8; i++) {
        v[i] = xp[lane + 32 * i];
        sum += v[i];
        sq += v[i] * v[i];
    }
#pragma unroll
    for (int off = 16; off; off >>= 1) {
        sum += __shfl_xor_sync(0xffffffffu, sum, off);
        sq  += __shfl_xor_sync(0xffffffffu, sq, off);
    }
    float mu = sum * (1.0f / 256.0f);
    float var = sq * (1.0f / 256.0f) - mu * mu;
    float inv = rsqrtf(var + 1e-5f);
    float* yp = y + (size_t)tok * DM;
#pragma unroll
    for (int i = 0; i < 8; i++) {
        int d = lane + 32 * i;
        yp[d] = (v[i] - mu) * inv * gam[d] + bet[d];
    }
}

// ---------------- attention: 1 thread per query, online softmax ----------------
// grid = B*HEADS blocks, 320 threads (one per query). K/V staged in two 160-key chunks.
__global__ void __launch_bounds__(320) attn_k(const float* __restrict__ qkv,
                                              float* __restrict__ out) {
    __shared__ float Ks[160 * 32];
    __shared__ float Vs[160 * 32];
    int b = blockIdx.x >> 3;
    int h = blockIdx.x & 7;
    int tid = threadIdx.x;
    const float* base = qkv + (size_t)b * SQ * 768;

    float q[32];
    const float* qp = base + (size_t)tid * 768 + h * 32;
    const float scale = 0.17677669529663687f;  // 1/sqrt(32)
#pragma unroll
    for (int d = 0; d < 32; d += 4) {
        float4 t = *(const float4*)(qp + d);
        q[d] = t.x * scale; q[d + 1] = t.y * scale; q[d + 2] = t.z * scale; q[d + 3] = t.w * scale;
    }

    float m = -1e30f, l = 0.f;
    float o[32];
#pragma unroll
    for (int d = 0; d < 32; d++) o[d] = 0.f;

    int row = tid >> 1;
    int part = (tid & 1) * 16;

    for (int c = 0; c < 2; c++) {
        __syncthreads();
        const float* kp = base + (size_t)(c * 160 + row) * 768 + 256 + h * 32 + part;
#pragma unroll
        for (int j = 0; j < 4; j++) {
            *(float4*)&Ks[row * 32 + part + j * 4] = *(const float4*)(kp + j * 4);
            *(float4*)&Vs[row * 32 + part + j * 4] = *(const float4*)(kp + 256 + j * 4);
        }
        __syncthreads();

        for (int key = 0; key < 160; key++) {
            const float* kr = &Ks[key * 32];
            float s = 0.f;
#pragma unroll
            for (int d = 0; d < 32; d++) s += q[d] * kr[d];
            float nm = fmaxf(m, s);
            float corr = __expf(m - nm);
            float p = __expf(s - nm);
            l = l * corr + p;
            const float* vr = &Vs[key * 32];
#pragma unroll
            for (int d = 0; d < 32; d++) o[d] = o[d] * corr + p * vr[d];
            m = nm;
        }
    }
    float inv = 1.f / l;
    float* op = out + ((size_t)(b * SQ + tid)) * DM + h * 32;
#pragma unroll
    for (int d = 0; d < 32; d += 4) {
        float4 r;
        r.x = o[d] * inv; r.y = o[d + 1] * inv; r.z = o[d + 2] * inv; r.w = o[d + 3] * inv;
        *(float4*)(op + d) = r;
    }
}

// ---------------- GEMM: C[M,N] = A[M,K] @ W[N,K]^T + epilogue ----------------
// 128x128 tile, BK=8, 256 threads, 8x8 per thread.
enum { EPL_PLAIN = 0, EPL_RES = 1, EPL_GELU = 2, EPL_IMGTOK = 3, EPL_GATE = 4 };

template <int MODE>
__global__ void __launch_bounds__(256) gemm_k(
    const float* __restrict__ A, const float* __restrict__ W,
    const float* __restrict__ bias, float* __restrict__ out,
    int M, int N, int K,
    const float* __restrict__ res, const float* __restrict__ extra,
    const int* __restrict__ idx) {
    __shared__ float As[8][132];
    __shared__ float Bs[8][132];
    const int t = threadIdx.x;
    const int m0 = blockIdx.y * 128;
    const int n0 = blockIdx.x * 128;
    const int lr = t >> 1;
    const int lk = (t & 1) << 2;
    const float* Ap = A + (size_t)(m0 + lr) * K + lk;
    const float* Wp = W + (size_t)(n0 + lr) * K + lk;
    const int ty = t >> 4, tx = t & 15;

    float acc[8][8];
#pragma unroll
    for (int i = 0; i < 8; i++)
#pragma unroll
        for (int j = 0; j < 8; j++) acc[i][j] = 0.f;

    for (int k0 = 0; k0 < K; k0 += 8) {
        float4 av = *(const float4*)(Ap + k0);
        float4 wv = *(const float4*)(Wp + k0);
        __syncthreads();
        As[lk + 0][lr] = av.x; As[lk + 1][lr] = av.y; As[lk + 2][lr] = av.z; As[lk + 3][lr] = av.w;
        Bs[lk + 0][lr] = wv.x; Bs[lk + 1][lr] = wv.y; Bs[lk + 2][lr] = wv.z; Bs[lk + 3][lr] = wv.w;
        __syncthreads();
#pragma unroll
        for (int kk = 0; kk < 8; kk++) {
            float4 a0 = *(const float4*)&As[kk][ty * 8];
            float4 a1 = *(const float4*)&As[kk][ty * 8 + 4];
            float4 b0 = *(const float4*)&Bs[kk][tx * 8];
            float4 b1 = *(const float4*)&Bs[kk][tx * 8 + 4];
            float ar[8] = {a0.x, a0.y, a0.z, a0.w, a1.x, a1.y, a1.z, a1.w};
            float br[8] = {b0.x, b0.y, b0.z, b0.w, b1.x, b1.y, b1.z, b1.w};
#pragma unroll
            for (int i = 0; i < 8; i++)
#pragma unroll
                for (int j = 0; j < 8; j++) acc[i][j] += ar[i] * br[j];
        }
    }

#pragma unroll
    for (int i = 0; i < 8; i++) {
        const int row = m0 + ty * 8 + i;
#pragma unroll
        for (int jv = 0; jv < 2; jv++) {
            const int col = n0 + tx * 8 + jv * 4;
            float4 bs = *(const float4*)&bias[col];
            float v[4];
            v[0] = acc[i][jv * 4 + 0] + bs.x;
            v[1] = acc[i][jv * 4 + 1] + bs.y;
            v[2] = acc[i][jv * 4 + 2] + bs.z;
            v[3] = acc[i][jv * 4 + 3] + bs.w;

            if (MODE == EPL_PLAIN) {
                float4 r = {v[0], v[1], v[2], v[3]};
                *(float4*)&out[(size_t)row * N + col] = r;
            } else if (MODE == EPL_RES) {
                float4 rr = *(const float4*)&res[(size_t)row * N + col];
                float4 r = {v[0] + rr.x, v[1] + rr.y, v[2] + rr.z, v[3] + rr.w};
                *(float4*)&out[(size_t)row * N + col] = r;
            } else if (MODE == EPL_GELU) {
                float4 r = {gelu_exact(v[0]), gelu_exact(v[1]), gelu_exact(v[2]), gelu_exact(v[3])};
                *(float4*)&out[(size_t)row * N + col] = r;
            } else if (MODE == EPL_IMGTOK) {
                int b = row >> 6, tt = row & 63;
                int yy = tt >> 3, xx = tt & 7;
                float4 r;
                r.x = v[0] + pos2d_val(yy, xx, col + 0);
                r.y = v[1] + pos2d_val(yy, xx, col + 1);
                r.z = v[2] + pos2d_val(yy, xx, col + 2);
                r.w = v[3] + pos2d_val(yy, xx, col + 3);
                *(float4*)&out[((size_t)(b * SQ + NCV + tt)) * DM + col] = r;
            } else {  // EPL_GATE
                int b = row >> 8, n = row & 255;
                float4 hc = *(const float4*)&res[(size_t)row * DM + col];
                float4 hn = *(const float4*)&extra[((size_t)(b * SQ + n)) * DM + col];
                float g0 = 1.f / (1.f + expf(-v[0]));
                float g1 = 1.f / (1.f + expf(-v[1]));
                float g2 = 1.f / (1.f + expf(-v[2]));
                float g3 = 1.f / (1.f + expf(-v[3]));
                float4 r;
                r.x = hc.x + g0 * (hn.x - hc.x);
                r.y = hc.y + g1 * (hn.y - hc.y);
                r.z = hc.z + g2 * (hn.z - hc.z);
                r.w = hc.w + g3 * (hn.w - hc.w);
                int p = idx[n];
                *(float4*)&out[((size_t)b * WSQ + p) * DM + col] = r;
            }
        }
    }
}

// ---------------- host launcher ----------------
extern "C" void kernel_launch(void* const* d_in, const int* in_sizes, int n_in,
                              void* d_out, int out_size) {
    const float* h_map   = (const float*)d_in[0];
    const float* frame   = (const float*)d_in[1];
    const int*   idx     = (const int*)  d_in[2];
    const float* Wqkv    = (const float*)d_in[3];
    const float* bqkv    = (const float*)d_in[4];
    const float* Wo      = (const float*)d_in[5];
    const float* bo      = (const float*)d_in[6];
    const float* ln1g    = (const float*)d_in[7];
    const float* ln1b    = (const float*)d_in[8];
    const float* W1      = (const float*)d_in[9];
    const float* b1      = (const float*)d_in[10];
    const float* W2      = (const float*)d_in[11];
    const float* b2      = (const float*)d_in[12];
    const float* ln2g    = (const float*)d_in[13];
    const float* ln2b    = (const float*)d_in[14];
    const float* nfg     = (const float*)d_in[15];
    const float* nfb     = (const float*)d_in[16];
    const float* patch_w = (const float*)d_in[17];
    const float* patch_b = (const float*)d_in[18];
    const float* gate_w  = (const float*)d_in[19];
    const float* gate_b  = (const float*)d_in[20];
    float* out = (float*)d_out;

    float *x, *ln, *qkv, *attn, *h1, *hcv, *cat, *patch;
    cudaGetSymbolAddress((void**)&x, g_x);
    cudaGetSymbolAddress((void**)&ln, g_ln);
    cudaGetSymbolAddress((void**)&qkv, g_qkv);
    cudaGetSymbolAddress((void**)&attn, g_attn);
    cudaGetSymbolAddress((void**)&h1, g_h1);
    cudaGetSymbolAddress((void**)&hcv, g_hcv);
    cudaGetSymbolAddress((void**)&cat, g_cat);
    cudaGetSymbolAddress((void**)&patch, g_patch);

    // pass-through copy of the whole map; gated scatter overwrites idx positions
    cudaMemcpyAsync(out, h_map, sizeof(float) * (size_t)BB * WSQ * DM,
                    cudaMemcpyDeviceToDevice, 0);

    // embed + patch tokens
    embed_k<<<16384, 256>>>(h_map, idx, hcv, x);
    im2col_k<<<(4096 * 768) / 256, 256>>>(frame, patch);
    gemm_k<EPL_IMGTOK><<<dim3(2, 32), 256>>>(patch, patch_w, patch_b, x,
                                             4096, 256, 768, nullptr, nullptr, nullptr);

    const int NTOK = BB * SQ;  // 20480
    for (int l = 0; l < NDEPTH; l++) {
        ln_k<<<NTOK / 8, 256>>>(x, ln, ln1g + l * 256, ln1b + l * 256);
        gemm_k<EPL_PLAIN><<<dim3(6, 160), 256>>>(ln, Wqkv + (size_t)l * 768 * 256,
                                                 bqkv + l * 768, qkv,
                                                 NTOK, 768, 256, nullptr, nullptr, nullptr);
        attn_k<<<BB * NHEADS, 320>>>(qkv, attn);
        gemm_k<EPL_RES><<<dim3(2, 160), 256>>>(attn, Wo + (size_t)l * 256 * 256,
                                               bo + l * 256, x,
                                               NTOK, 256, 256, x, nullptr, nullptr);
        ln_k<<<NTOK / 8, 256>>>(x, ln, ln2g + l * 256, ln2b + l * 256);
        gemm_k<EPL_GELU><<<dim3(8, 160), 256>>>(ln, W1 + (size_t)l * 1024 * 256,
                                                b1 + l * 1024, h1,
                                                NTOK, 1024, 256, nullptr, nullptr, nullptr);
        gemm_k<EPL_RES><<<dim3(2, 160), 256>>>(h1, W2 + (size_t)l * 256 * 1024,
                                               b2 + l * 256, x,
                                               NTOK, 256, 1024, x, nullptr, nullptr);
    }

    // final LN + gated scatter
    ln_k<<<NTOK / 8, 256>>>(x, ln, nfg, nfb);
    cat_k<<<(16384 * 512) / 256, 256>>>(hcv, ln, cat);
    gemm_k<EPL_GATE><<<dim3(2, 128), 256>>>(cat, gate_w, gate_b, out,
                                            16384, 256, 512, hcv, ln, idx);
}

// round 3
// speedup vs baseline: 1.7862x; 1.7862x over previous
#include <cuda_runtime.h>
#include <cuda_bf16.h>
#include <math.h>
#include <stdint.h>

#define BB 64
#define SQ 320
#define NCV 256
#define DM 256
#define HIDN 1024
#define NHEADS 8
#define NDEPTH 6
#define WSQ 1089

// ---------------- device scratch ----------------
__device__ float g_x[(size_t)BB * SQ * DM];
__device__ float g_ln[(size_t)BB * SQ * DM];
__device__ float g_qkv[(size_t)BB * SQ * 3 * DM];
__device__ float g_attn[(size_t)BB * SQ * DM];
__device__ float g_h1[(size_t)BB * SQ * HIDN];
__device__ float g_hcv[(size_t)BB * NCV * DM];
__device__ float g_cat[(size_t)BB * NCV * 2 * DM];
__device__ float g_patch[(size_t)BB * 64 * 768];

// ---------------- helpers ----------------
__device__ __forceinline__ float pos2d_val(int yy, int xx, int d) {
    int dd = d & 127;
    int i = dd >> 1;
    float freq = expf((float)(2 * i) * (-0.07195578415606394f));
    float coord = (d < 128) ? (float)yy : (float)xx;
    float ang = coord * freq;
    return (d & 1) ? cosf(ang) : sinf(ang);
}

__device__ __forceinline__ float gelu_exact(float v) {
    return 0.5f * v * (1.0f + erff(v * 0.70710678118654752f));
}

// ---------------- small elementwise kernels ----------------
__global__ void __launch_bounds__(256) embed_k(const float* __restrict__ h_map,
                                               const int* __restrict__ idx,
                                               float* __restrict__ hcv,
                                               float* __restrict__ x) {
    int gid = blockIdx.x * 256 + threadIdx.x;
    int d = gid & 255;
    int n = (gid >> 8) & 255;
    int b = gid >> 16;
    int p = idx[n];
    float h = h_map[((size_t)b * WSQ + p) * DM + d];
    hcv[gid] = h;
    x[((size_t)(b * SQ + n)) * DM + d] = h + pos2d_val(p / 33, p % 33, d);
}

__global__ void __launch_bounds__(256) im2col_k(const float* __restrict__ frame,
                                                float* __restrict__ patches) {
    int gid = blockIdx.x * 256 + threadIdx.x;
    int k = gid % 768;
    int m = gid / 768;
    int c = k >> 8;
    int r = (k >> 4) & 15;
    int q = k & 15;
    int t = m & 63, b = m >> 6;
    int yy = (t >> 3) * 16 + r;
    int xx = (t & 7) * 16 + q;
    patches[gid] = frame[(((size_t)b * 3 + c) * 128 + yy) * 128 + xx];
}

__global__ void __launch_bounds__(256) cat_k(const float* __restrict__ hcv,
                                             const float* __restrict__ lnx,
                                             float* __restrict__ cat) {
    int gid = blockIdx.x * 256 + threadIdx.x;
    int dcol = gid & 511;
    int m = gid >> 9;
    int b = m >> 8, n = m & 255;
    cat[gid] = (dcol < 256) ? hcv[((size_t)m << 8) + dcol]
                            : lnx[(((size_t)(b * SQ + n)) << 8) + (dcol - 256)];
}

__global__ void __launch_bounds__(256) ln_k(const float* __restrict__ x,
                                            float* __restrict__ y,
                                            const float* __restrict__ gam,
                                            const float* __restrict__ bet) {
    int warp = threadIdx.x >> 5;
    int lane = threadIdx.x & 31;
    int tok = blockIdx.x * 8 + warp;
    const float* xp = x + (size_t)tok * DM;
    float v[8];
    float sum = 0.f, sq = 0.f;
#pragma unroll
    for (int i = 0; i < 8; i++) {
        v[i] = xp[lane + 32 * i];
        sum += v[i];
        sq += v[i] * v[i];
    }
#pragma unroll
    for (int off = 16; off; off >>= 1) {
        sum += __shfl_xor_sync(0xffffffffu, sum, off);
        sq  += __shfl_xor_sync(0xffffffffu, sq, off);
    }
    float mu = sum * (1.0f / 256.0f);
    float var = sq * (1.0f / 256.0f) - mu * mu;
    float inv = rsqrtf(var + 1e-5f);
    float* yp = y + (size_t)tok * DM;
#pragma unroll
    for (int i = 0; i < 8; i++) {
        int d = lane + 32 * i;
        yp[d] = (v[i] - mu) * inv * gam[d] + bet[d];
    }
}

__global__ void __launch_bounds__(320) attn_k(const float* __restrict__ qkv,
                                              float* __restrict__ out) {
    __shared__ float Ks[160 * 32];
    __shared__ float Vs[160 * 32];
    int b = blockIdx.x >> 3;
    int h = blockIdx.x & 7;
    int tid = threadIdx.x;
    const float* base = qkv + (size_t)b * SQ * 768;

    float q[32];
    const float* qp = base + (size_t)tid * 768 + h * 32;
    const float scale = 0.17677669529663687f;
#pragma unroll
    for (int d = 0; d < 32; d += 4) {
        float4 t = *(const float4*)(qp + d);
        q[d] = t.x * scale; q[d + 1] = t.y * scale; q[d + 2] = t.z * scale; q[d + 3] = t.w * scale;
    }

    float m = -1e30f, l = 0.f;
    float o[32];
#pragma unroll
    for (int d = 0; d < 32; d++) o[d] = 0.f;

    int row = tid >> 1;
    int part = (tid & 1) * 16;

    for (int c = 0; c < 2; c++) {
        __syncthreads();
        const float* kp = base + (size_t)(c * 160 + row) * 768 + 256 + h * 32 + part;
#pragma unroll
        for (int j = 0; j < 4; j++) {
            *(float4*)&Ks[row * 32 + part + j * 4] = *(const float4*)(kp + j * 4);
            *(float4*)&Vs[row * 32 + part + j * 4] = *(const float4*)(kp + 256 + j * 4);
        }
        __syncthreads();

        for (int key = 0; key < 160; key++) {
            const float* kr = &Ks[key * 32];
            float s = 0.f;
#pragma unroll
            for (int d = 0; d < 32; d++) s += q[d] * kr[d];
            float nm = fmaxf(m, s);
            float corr = __expf(m - nm);
            float p = __expf(s - nm);
            l = l * corr + p;
            const float* vr = &Vs[key * 32];
#pragma unroll
            for (int d = 0; d < 32; d++) o[d] = o[d] * corr + p * vr[d];
            m = nm;
        }
    }
    float inv = 1.f / l;
    float* op = out + ((size_t)(b * SQ + tid)) * DM + h * 32;
#pragma unroll
    for (int d = 0; d < 32; d += 4) {
        float4 r;
        r.x = o[d] * inv; r.y = o[d + 1] * inv; r.z = o[d + 2] * inv; r.w = o[d + 3] * inv;
        *(float4*)(op + d) = r;
    }
}

// ================= HMMA (mma.sync) bf16 3-split GEMM =================
// C[M,N] = A[M,K] @ W[N,K]^T + bias (+mode epilogue), fp32 in/out.
// CTA 128x128, 256 thr (8 warps 4x2), warp tile 32x64, BK=64, single-buffer smem.
enum { EPL_PLAIN = 0, EPL_RES = 1, EPL_GELU = 2, EPL_IMGTOK = 3, EPL_GATE = 4 };

// smem: 4 tiles of 128 rows x 72 bf16 (pad 64->72 kills bank conflicts)
#define TROW_B 144              // bytes per padded row
#define TILE_B (128 * TROW_B)   // 18432
#define GSMEM_BYTES (4 * TILE_B)  // 73728

__device__ __forceinline__ void mma16816(float* c, const uint32_t* a, const uint32_t* b) {
    asm volatile(
        "mma.sync.aligned.m16n8k16.row.col.f32.bf16.bf16.f32 "
        "{%0,%1,%2,%3}, {%4,%5,%6,%7}, {%8,%9}, {%0,%1,%2,%3};\n"
        : "+f"(c[0]), "+f"(c[1]), "+f"(c[2]), "+f"(c[3])
        : "r"(a[0]), "r"(a[1]), "r"(a[2]), "r"(a[3]), "r"(b[0]), "r"(b[1]));
}

__device__ __forceinline__ void cvt_store4(char* sm_hi, char* sm_lo,
                                           uint32_t off, float4 v) {
    __nv_bfloat16 hx = __float2bfloat16(v.x);
    __nv_bfloat16 hy = __float2bfloat16(v.y);
    __nv_bfloat16 hz = __float2bfloat16(v.z);
    __nv_bfloat16 hw = __float2bfloat16(v.w);
    float rx = v.x - __bfloat162float(hx);
    float ry = v.y - __bfloat162float(hy);
    float rz = v.z - __bfloat162float(hz);
    float rw = v.w - __bfloat162float(hw);
    __nv_bfloat16 lx = __float2bfloat16(rx);
    __nv_bfloat16 ly = __float2bfloat16(ry);
    __nv_bfloat16 lz = __float2bfloat16(rz);
    __nv_bfloat16 lw = __float2bfloat16(rw);
    uint32_t h0 = ((uint32_t)__bfloat16_as_ushort(hy) << 16) | __bfloat16_as_ushort(hx);
    uint32_t h1 = ((uint32_t)__bfloat16_as_ushort(hw) << 16) | __bfloat16_as_ushort(hz);
    uint32_t l0 = ((uint32_t)__bfloat16_as_ushort(ly) << 16) | __bfloat16_as_ushort(lx);
    uint32_t l1 = ((uint32_t)__bfloat16_as_ushort(lw) << 16) | __bfloat16_as_ushort(lz);
    *(uint2*)(sm_hi + off) = make_uint2(h0, h1);
    *(uint2*)(sm_lo + off) = make_uint2(l0, l1);
}

template <int MODE>
__device__ __forceinline__ void epi_store2(
    float* __restrict__ out, int N, int row, int col, float vx, float vy,
    const float* __restrict__ bias, const float* __restrict__ res,
    const float* __restrict__ extra, const int* __restrict__ idx) {
    float2 bb = *(const float2*)(bias + col);
    vx += bb.x;
    vy += bb.y;
    if (MODE == EPL_PLAIN) {
        *(float2*)&out[(size_t)row * N + col] = make_float2(vx, vy);
    } else if (MODE == EPL_RES) {
        float2 rr = *(const float2*)&res[(size_t)row * N + col];
        *(float2*)&out[(size_t)row * N + col] = make_float2(vx + rr.x, vy + rr.y);
    } else if (MODE == EPL_GELU) {
        *(float2*)&out[(size_t)row * N + col] =
            make_float2(gelu_exact(vx), gelu_exact(vy));
    } else if (MODE == EPL_IMGTOK) {
        int b = row >> 6, tt = row & 63;
        int yy = tt >> 3, xx = tt & 7;
        vx += pos2d_val(yy, xx, col);
        vy += pos2d_val(yy, xx, col + 1);
        *(float2*)&out[((size_t)(b * SQ + NCV + tt)) * DM + col] = make_float2(vx, vy);
    } else {  // EPL_GATE
        int b = row >> 8, n = row & 255;
        int p = idx[n];
        float2 hc = *(const float2*)&res[(size_t)row * DM + col];
        float2 hn = *(const float2*)&extra[((size_t)(b * SQ + n)) * DM + col];
        float g0 = 1.f / (1.f + expf(-vx));
        float g1 = 1.f / (1.f + expf(-vy));
        float2 r;
        r.x = hc.x + g0 * (hn.x - hc.x);
        r.y = hc.y + g1 * (hn.y - hc.y);
        *(float2*)&out[((size_t)b * WSQ + p) * DM + col] = r;
    }
}

template <int MODE>
__global__ void __launch_bounds__(256, 2) mma_gemm_k(
    const float* __restrict__ A, const float* __restrict__ W,
    const float* __restrict__ bias, float* __restrict__ out,
    int M, int N, int K,
    const float* __restrict__ res, const float* __restrict__ extra,
    const int* __restrict__ idx) {
    extern __shared__ char sm[];
    char* AH = sm;
    char* AL = sm + TILE_B;
    char* BH = sm + 2 * TILE_B;
    char* BL = sm + 3 * TILE_B;

    const int tid = threadIdx.x;
    const int lane = tid & 31;
    const int w = tid >> 5;
    const int wm = w >> 1;   // 0..3 -> M offset wm*32
    const int wn = w & 1;    // 0..1 -> N offset wn*64
    const int m0 = blockIdx.y * 128;
    const int n0 = blockIdx.x * 128;

    float acc[2][8][4];
#pragma unroll
    for (int i = 0; i < 2; i++)
#pragma unroll
        for (int j = 0; j < 8; j++)
#pragma unroll
            for (int q = 0; q < 4; q++) acc[i][j][q] = 0.f;

    const int ldr = tid >> 4;   // 0..15
    const int ldc = tid & 15;   // float4 col 0..15 (covers 64 floats)
    const uint32_t soff = (uint32_t)ldr * TROW_B + (uint32_t)ldc * 8;

    for (int k0 = 0; k0 < K; k0 += 64) {
        __syncthreads();
#pragma unroll 2
        for (int p = 0; p < 8; p++) {
            int row = ldr + p * 16;
            float4 va = *(const float4*)(A + (size_t)(m0 + row) * K + k0 + ldc * 4);
            float4 vb = *(const float4*)(W + (size_t)(n0 + row) * K + k0 + ldc * 4);
            cvt_store4(AH, AL, soff + p * 16 * TROW_B, va);
            cvt_store4(BH, BL, soff + p * 16 * TROW_B, vb);
        }
        __syncthreads();

#pragma unroll
        for (int ks = 0; ks < 4; ks++) {
            const int kb = (ks * 16 + (lane & 3) * 2) * 2;  // byte offset of k pair
            uint32_t ah[2][4], al[2][4];
#pragma unroll
            for (int mf = 0; mf < 2; mf++) {
                int r = wm * 32 + mf * 16 + (lane >> 2);
                int o1 = r * TROW_B + kb;
                int o2 = o1 + 8 * TROW_B;
                ah[mf][0] = *(const uint32_t*)(AH + o1);
                ah[mf][1] = *(const uint32_t*)(AH + o2);
                ah[mf][2] = *(const uint32_t*)(AH + o1 + 16);
                ah[mf][3] = *(const uint32_t*)(AH + o2 + 16);
                al[mf][0] = *(const uint32_t*)(AL + o1);
                al[mf][1] = *(const uint32_t*)(AL + o2);
                al[mf][2] = *(const uint32_t*)(AL + o1 + 16);
                al[mf][3] = *(const uint32_t*)(AL + o2 + 16);
            }
#pragma unroll
            for (int nf = 0; nf < 8; nf++) {
                int nrow = wn * 64 + nf * 8 + (lane >> 2);
                int ob = nrow * TROW_B + kb;
                uint32_t bh[2], bl[2];
                bh[0] = *(const uint32_t*)(BH + ob);
                bh[1] = *(const uint32_t*)(BH + ob + 16);
                bl[0] = *(const uint32_t*)(BL + ob);
                bl[1] = *(const uint32_t*)(BL + ob + 16);
#pragma unroll
                for (int mf = 0; mf < 2; mf++) {
                    mma16816(acc[mf][nf], ah[mf], bh);
                    mma16816(acc[mf][nf], ah[mf], bl);
                    mma16816(acc[mf][nf], al[mf], bh);
                }
            }
        }
    }

    // epilogue: write fragments directly
#pragma unroll
    for (int mf = 0; mf < 2; mf++) {
        int row = m0 + wm * 32 + mf * 16 + (lane >> 2);
#pragma unroll
        for (int nf = 0; nf < 8; nf++) {
            int col = n0 + wn * 64 + nf * 8 + (lane & 3) * 2;
            epi_store2<MODE>(out, N, row, col, acc[mf][nf][0], acc[mf][nf][1],
                             bias, res, extra, idx);
            epi_store2<MODE>(out, N, row + 8, col, acc[mf][nf][2], acc[mf][nf][3],
                             bias, res, extra, idx);
        }
    }
}

// ---------------- host launcher ----------------
extern "C" void kernel_launch(void* const* d_in, const int* in_sizes, int n_in,
                              void* d_out, int out_size) {
    const float* h_map   = (const float*)d_in[0];
    const float* frame   = (const float*)d_in[1];
    const int*   idx     = (const int*)  d_in[2];
    const float* Wqkv    = (const float*)d_in[3];
    const float* bqkv    = (const float*)d_in[4];
    const float* Wo      = (const float*)d_in[5];
    const float* bo      = (const float*)d_in[6];
    const float* ln1g    = (const float*)d_in[7];
    const float* ln1b    = (const float*)d_in[8];
    const float* W1      = (const float*)d_in[9];
    const float* b1      = (const float*)d_in[10];
    const float* W2      = (const float*)d_in[11];
    const float* b2      = (const float*)d_in[12];
    const float* ln2g    = (const float*)d_in[13];
    const float* ln2b    = (const float*)d_in[14];
    const float* nfg     = (const float*)d_in[15];
    const float* nfb     = (const float*)d_in[16];
    const float* patch_w = (const float*)d_in[17];
    const float* patch_b = (const float*)d_in[18];
    const float* gate_w  = (const float*)d_in[19];
    const float* gate_b  = (const float*)d_in[20];
    float* out = (float*)d_out;

    float *x, *ln, *qkv, *attn, *h1, *hcv, *cat, *patch;
    cudaGetSymbolAddress((void**)&x, g_x);
    cudaGetSymbolAddress((void**)&ln, g_ln);
    cudaGetSymbolAddress((void**)&qkv, g_qkv);
    cudaGetSymbolAddress((void**)&attn, g_attn);
    cudaGetSymbolAddress((void**)&h1, g_h1);
    cudaGetSymbolAddress((void**)&hcv, g_hcv);
    cudaGetSymbolAddress((void**)&cat, g_cat);
    cudaGetSymbolAddress((void**)&patch, g_patch);

    cudaFuncSetAttribute(mma_gemm_k<EPL_PLAIN>,  cudaFuncAttributeMaxDynamicSharedMemorySize, GSMEM_BYTES);
    cudaFuncSetAttribute(mma_gemm_k<EPL_RES>,    cudaFuncAttributeMaxDynamicSharedMemorySize, GSMEM_BYTES);
    cudaFuncSetAttribute(mma_gemm_k<EPL_GELU>,   cudaFuncAttributeMaxDynamicSharedMemorySize, GSMEM_BYTES);
    cudaFuncSetAttribute(mma_gemm_k<EPL_IMGTOK>, cudaFuncAttributeMaxDynamicSharedMemorySize, GSMEM_BYTES);
    cudaFuncSetAttribute(mma_gemm_k<EPL_GATE>,   cudaFuncAttributeMaxDynamicSharedMemorySize, GSMEM_BYTES);

    // pass-through copy; gated scatter overwrites idx positions
    cudaMemcpyAsync(out, h_map, sizeof(float) * (size_t)BB * WSQ * DM,
                    cudaMemcpyDeviceToDevice, 0);

    embed_k<<<16384, 256>>>(h_map, idx, hcv, x);
    im2col_k<<<(4096 * 768) / 256, 256>>>(frame, patch);
    mma_gemm_k<EPL_IMGTOK><<<dim3(2, 32), 256, GSMEM_BYTES>>>(
        patch, patch_w, patch_b, x, 4096, 256, 768, nullptr, nullptr, nullptr);

    const int NTOK = BB * SQ;  // 20480
    for (int l = 0; l < NDEPTH; l++) {
        ln_k<<<NTOK / 8, 256>>>(x, ln, ln1g + l * 256, ln1b + l * 256);
        mma_gemm_k<EPL_PLAIN><<<dim3(6, 160), 256, GSMEM_BYTES>>>(
            ln, Wqkv + (size_t)l * 768 * 256, bqkv + l * 768, qkv,
            NTOK, 768, 256, nullptr, nullptr, nullptr);
        attn_k<<<BB * NHEADS, 320>>>(qkv, attn);
        mma_gemm_k<EPL_RES><<<dim3(2, 160), 256, GSMEM_BYTES>>>(
            attn, Wo + (size_t)l * 256 * 256, bo + l * 256, x,
            NTOK, 256, 256, x, nullptr, nullptr);
        ln_k<<<NTOK / 8, 256>>>(x, ln, ln2g + l * 256, ln2b + l * 256);
        mma_gemm_k<EPL_GELU><<<dim3(8, 160), 256, GSMEM_BYTES>>>(
            ln, W1 + (size_t)l * 1024 * 256, b1 + l * 1024, h1,
            NTOK, 1024, 256, nullptr, nullptr, nullptr);
        mma_gemm_k<EPL_RES><<<dim3(2, 160), 256, GSMEM_BYTES>>>(
            h1, W2 + (size_t)l * 256 * 1024, b2 + l * 256, x,
            NTOK, 256, 1024, x, nullptr, nullptr);
    }

    ln_k<<<NTOK / 8, 256>>>(x, ln, nfg, nfb);
    cat_k<<<(16384 * 512) / 256, 256>>>(hcv, ln, cat);
    mma_gemm_k<EPL_GATE><<<dim3(2, 128), 256, GSMEM_BYTES>>>(
        cat, gate_w, gate_b, out, 16384, 256, 512, hcv, ln, idx);
}

// round 4
// speedup vs baseline: 2.1088x; 1.1806x over previous
#include <cuda_runtime.h>
#include <cuda_bf16.h>
#include <math.h>
#include <stdint.h>

#define BB 64
#define SQ 320
#define NCV 256
#define DM 256
#define HIDN 1024
#define NHEADS 8
#define NDEPTH 6
#define WSQ 1089

// ---------------- device scratch ----------------
__device__ float g_x[(size_t)BB * SQ * DM];
__device__ float g_ln[(size_t)BB * SQ * DM];     // final LN fp32 (gate 'extra')
__device__ float g_qkv[(size_t)BB * SQ * 3 * DM];
__device__ float g_hcv[(size_t)BB * NCV * DM];

// bf16 hi/lo activation buffers
__device__ __nv_bfloat16 g_lnh[(size_t)BB * SQ * DM],   g_lnl[(size_t)BB * SQ * DM];
__device__ __nv_bfloat16 g_ath[(size_t)BB * SQ * DM],   g_atl[(size_t)BB * SQ * DM];
__device__ __nv_bfloat16 g_h1h[(size_t)BB * SQ * HIDN], g_h1l[(size_t)BB * SQ * HIDN];
__device__ __nv_bfloat16 g_cth[(size_t)BB * NCV * 2 * DM], g_ctl[(size_t)BB * NCV * 2 * DM];
__device__ __nv_bfloat16 g_pth[(size_t)BB * 64 * 768], g_ptl[(size_t)BB * 64 * 768];

// bf16 hi/lo weights (one pool, fixed offsets)
#define WOFF_QKV   0u
#define WOFF_WO    1179648u
#define WOFF_W1    1572864u
#define WOFF_W2    3145728u
#define WOFF_PW    4718592u
#define WOFF_GW    4915200u
#define WPOOL_N    5046272u
__device__ __nv_bfloat16 g_wh[WPOOL_N], g_wl[WPOOL_N];

// ---------------- helpers ----------------
__device__ __forceinline__ float pos2d_val(int yy, int xx, int d) {
    int dd = d & 127;
    int i = dd >> 1;
    float freq = expf((float)(2 * i) * (-0.07195578415606394f));
    float coord = (d < 128) ? (float)yy : (float)xx;
    float ang = coord * freq;
    return (d & 1) ? cosf(ang) : sinf(ang);
}

__device__ __forceinline__ float gelu_exact(float v) {
    return 0.5f * v * (1.0f + erff(v * 0.70710678118654752f));
}

__device__ __forceinline__ void split1(float v, __nv_bfloat16& h, __nv_bfloat16& l) {
    h = __float2bfloat16(v);
    l = __float2bfloat16(v - __bfloat162float(h));
}

// ---------------- weight fp32 -> bf16 hi/lo ----------------
__global__ void __launch_bounds__(256) wcvt_k(const float* __restrict__ in,
                                              __nv_bfloat16* __restrict__ h,
                                              __nv_bfloat16* __restrict__ l) {
    int i = blockIdx.x * 256 + threadIdx.x;   // one float4 per thread
    float4 v = ((const float4*)in)[i];
    __nv_bfloat16 hx, hy, hz, hw, lx, ly, lz, lw;
    split1(v.x, hx, lx); split1(v.y, hy, ly);
    split1(v.z, hz, lz); split1(v.w, hw, lw);
    __nv_bfloat162* hp = (__nv_bfloat162*)(h + (size_t)i * 4);
    __nv_bfloat162* lp = (__nv_bfloat162*)(l + (size_t)i * 4);
    hp[0] = __nv_bfloat162{hx, hy}; hp[1] = __nv_bfloat162{hz, hw};
    lp[0] = __nv_bfloat162{lx, ly}; lp[1] = __nv_bfloat162{lz, lw};
}

// ---------------- embed / im2col / cat ----------------
__global__ void __launch_bounds__(256) embed_k(const float* __restrict__ h_map,
                                               const int* __restrict__ idx,
                                               float* __restrict__ hcv,
                                               float* __restrict__ x) {
    int gid = blockIdx.x * 256 + threadIdx.x;
    int d = gid & 255;
    int n = (gid >> 8) & 255;
    int b = gid >> 16;
    int p = idx[n];
    float h = h_map[((size_t)b * WSQ + p) * DM + d];
    hcv[gid] = h;
    x[((size_t)(b * SQ + n)) * DM + d] = h + pos2d_val(p / 33, p % 33, d);
}

__global__ void __launch_bounds__(256) im2col_k(const float* __restrict__ frame,
                                                __nv_bfloat16* __restrict__ ph,
                                                __nv_bfloat16* __restrict__ pl) {
    int gid = blockIdx.x * 256 + threadIdx.x;   // < 4096*768
    int k = gid % 768;
    int m = gid / 768;
    int c = k >> 8;
    int r = (k >> 4) & 15;
    int q = k & 15;
    int t = m & 63, b = m >> 6;
    int yy = (t >> 3) * 16 + r;
    int xx = (t & 7) * 16 + q;
    float v = frame[(((size_t)b * 3 + c) * 128 + yy) * 128 + xx];
    split1(v, ph[gid], pl[gid]);
}

__global__ void __launch_bounds__(256) cat_k(const float* __restrict__ hcv,
                                             const float* __restrict__ lnx,
                                             __nv_bfloat16* __restrict__ ch,
                                             __nv_bfloat16* __restrict__ cl) {
    int gid = blockIdx.x * 256 + threadIdx.x;   // < 16384*512
    int dcol = gid & 511;
    int m = gid >> 9;
    int b = m >> 8, n = m & 255;
    float v = (dcol < 256) ? hcv[((size_t)m << 8) + dcol]
                           : lnx[(((size_t)(b * SQ + n)) << 8) + (dcol - 256)];
    split1(v, ch[gid], cl[gid]);
}

// ---------------- LayerNorm: emits bf16 hi/lo (+optional fp32) ----------------
template <bool F32OUT>
__global__ void __launch_bounds__(256) ln_k(const float* __restrict__ x,
                                            float* __restrict__ y,
                                            __nv_bfloat16* __restrict__ yh,
                                            __nv_bfloat16* __restrict__ yl,
                                            const float* __restrict__ gam,
                                            const float* __restrict__ bet) {
    int warp = threadIdx.x >> 5;
    int lane = threadIdx.x & 31;
    int tok = blockIdx.x * 8 + warp;
    const float* xp = x + (size_t)tok * DM;
    float v[8];
    float sum = 0.f, sq = 0.f;
#pragma unroll
    for (int i = 0; i < 8; i++) {
        v[i] = xp[lane + 32 * i];
        sum += v[i];
        sq += v[i] * v[i];
    }
#pragma unroll
    for (int off = 16; off; off >>= 1) {
        sum += __shfl_xor_sync(0xffffffffu, sum, off);
        sq  += __shfl_xor_sync(0xffffffffu, sq, off);
    }
    float mu = sum * (1.0f / 256.0f);
    float var = sq * (1.0f / 256.0f) - mu * mu;
    float inv = rsqrtf(var + 1e-5f);
#pragma unroll
    for (int i = 0; i < 8; i++) {
        int d = lane + 32 * i;
        float r = (v[i] - mu) * inv * gam[d] + bet[d];
        if (F32OUT) y[(size_t)tok * DM + d] = r;
        split1(r, yh[(size_t)tok * DM + d], yl[(size_t)tok * DM + d]);
    }
}

// ---------------- attention (emits bf16 hi/lo) ----------------
__global__ void __launch_bounds__(320) attn_k(const float* __restrict__ qkv,
                                              __nv_bfloat16* __restrict__ oh,
                                              __nv_bfloat16* __restrict__ ol) {
    __shared__ float Ks[160 * 32];
    __shared__ float Vs[160 * 32];
    int b = blockIdx.x >> 3;
    int h = blockIdx.x & 7;
    int tid = threadIdx.x;
    const float* base = qkv + (size_t)b * SQ * 768;

    float q[32];
    const float* qp = base + (size_t)tid * 768 + h * 32;
    const float scale = 0.17677669529663687f;
#pragma unroll
    for (int d = 0; d < 32; d += 4) {
        float4 t = *(const float4*)(qp + d);
        q[d] = t.x * scale; q[d + 1] = t.y * scale; q[d + 2] = t.z * scale; q[d + 3] = t.w * scale;
    }

    float m = -1e30f, l = 0.f;
    float o[32];
#pragma unroll
    for (int d = 0; d < 32; d++) o[d] = 0.f;

    int row = tid >> 1;
    int part = (tid & 1) * 16;

    for (int c = 0; c < 2; c++) {
        __syncthreads();
        const float* kp = base + (size_t)(c * 160 + row) * 768 + 256 + h * 32 + part;
#pragma unroll
        for (int j = 0; j < 4; j++) {
            *(float4*)&Ks[row * 32 + part + j * 4] = *(const float4*)(kp + j * 4);
            *(float4*)&Vs[row * 32 + part + j * 4] = *(const float4*)(kp + 256 + j * 4);
        }
        __syncthreads();

        for (int key = 0; key < 160; key++) {
            const float* kr = &Ks[key * 32];
            float s = 0.f;
#pragma unroll
            for (int d = 0; d < 32; d++) s += q[d] * kr[d];
            float nm = fmaxf(m, s);
            float corr = __expf(m - nm);
            float p = __expf(s - nm);
            l = l * corr + p;
            const float* vr = &Vs[key * 32];
#pragma unroll
            for (int d = 0; d < 32; d++) o[d] = o[d] * corr + p * vr[d];
            m = nm;
        }
    }
    float inv = 1.f / l;
    size_t obase = ((size_t)(b * SQ + tid)) * DM + h * 32;
#pragma unroll
    for (int d = 0; d < 32; d += 2) {
        __nv_bfloat16 h0, l0, h1, l1;
        split1(o[d] * inv, h0, l0);
        split1(o[d + 1] * inv, h1, l1);
        *(__nv_bfloat162*)(oh + obase + d) = __nv_bfloat162{h0, h1};
        *(__nv_bfloat162*)(ol + obase + d) = __nv_bfloat162{l0, l1};
    }
}

// ================= HMMA pipelined 3-split GEMM =================
// C[M,N] = A @ W^T + bias (+epilogue). A,W given as bf16 hi/lo (K-major).
// CTA 128x128, BK=64, 256 thr (8 warps 4x2, warp 32x64), 3-stage cp.async.
enum { EPL_PLAIN = 0, EPL_RES = 1, EPL_GELU = 2, EPL_IMGTOK = 3, EPL_GATE = 4 };

#define STG_B 65536u      // per-stage smem: Ah|Al|Bh|Bl, 16KB each
#define GSMEM_BYTES (3u * STG_B)

__device__ __forceinline__ uint32_t smem_u32(const void* p) {
    uint32_t a;
    asm("{ .reg .u64 t; cvta.to.shared.u64 t, %1; cvt.u32.u64 %0, t; }" : "=r"(a) : "l"(p));
    return a;
}

__device__ __forceinline__ void cp16(uint32_t dst, const void* src) {
    asm volatile("cp.async.cg.shared.global [%0], [%1], 16;" :: "r"(dst), "l"(src));
}

__device__ __forceinline__ void ldsm4(uint32_t* r, uint32_t addr) {
    asm volatile("ldmatrix.sync.aligned.m8n8.x4.shared.b16 {%0,%1,%2,%3}, [%4];"
                 : "=r"(r[0]), "=r"(r[1]), "=r"(r[2]), "=r"(r[3]) : "r"(addr));
}

__device__ __forceinline__ void mma16816(float* c, const uint32_t* a, const uint32_t* b) {
    asm volatile(
        "mma.sync.aligned.m16n8k16.row.col.f32.bf16.bf16.f32 "
        "{%0,%1,%2,%3}, {%4,%5,%6,%7}, {%8,%9}, {%0,%1,%2,%3};\n"
        : "+f"(c[0]), "+f"(c[1]), "+f"(c[2]), "+f"(c[3])
        : "r"(a[0]), "r"(a[1]), "r"(a[2]), "r"(a[3]), "r"(b[0]), "r"(b[1]));
}

template <int MODE>
__device__ __forceinline__ void epi_store2(
    float* __restrict__ out, __nv_bfloat16* __restrict__ outh,
    __nv_bfloat16* __restrict__ outl, int N, int row, int col, float vx, float vy,
    const float* __restrict__ bias, const float* __restrict__ res,
    const float* __restrict__ extra, const int* __restrict__ idx) {
    float2 bb = *(const float2*)(bias + col);
    vx += bb.x;
    vy += bb.y;
    if (MODE == EPL_PLAIN) {
        *(float2*)&out[(size_t)row * N + col] = make_float2(vx, vy);
    } else if (MODE == EPL_RES) {
        float2 rr = *(const float2*)&res[(size_t)row * N + col];
        *(float2*)&out[(size_t)row * N + col] = make_float2(vx + rr.x, vy + rr.y);
    } else if (MODE == EPL_GELU) {
        float gx = gelu_exact(vx), gy = gelu_exact(vy);
        __nv_bfloat16 h0, l0, h1, l1;
        split1(gx, h0, l0);
        split1(gy, h1, l1);
        *(__nv_bfloat162*)&outh[(size_t)row * N + col] = __nv_bfloat162{h0, h1};
        *(__nv_bfloat162*)&outl[(size_t)row * N + col] = __nv_bfloat162{l0, l1};
    } else if (MODE == EPL_IMGTOK) {
        int b = row >> 6, tt = row & 63;
        int yy = tt >> 3, xx = tt & 7;
        vx += pos2d_val(yy, xx, col);
        vy += pos2d_val(yy, xx, col + 1);
        *(float2*)&out[((size_t)(b * SQ + NCV + tt)) * DM + col] = make_float2(vx, vy);
    } else {  // EPL_GATE
        int b = row >> 8, n = row & 255;
        int p = idx[n];
        float2 hc = *(const float2*)&res[(size_t)row * DM + col];
        float2 hn = *(const float2*)&extra[((size_t)(b * SQ + n)) * DM + col];
        float g0 = 1.f / (1.f + expf(-vx));
        float g1 = 1.f / (1.f + expf(-vy));
        float2 r;
        r.x = hc.x + g0 * (hn.x - hc.x);
        r.y = hc.y + g1 * (hn.y - hc.y);
        *(float2*)&out[((size_t)b * WSQ + p) * DM + col] = r;
    }
}

template <int MODE>
__global__ void __launch_bounds__(256, 1) mma_gemm_k(
    const __nv_bfloat16* __restrict__ Ah, const __nv_bfloat16* __restrict__ Al,
    const __nv_bfloat16* __restrict__ Bh, const __nv_bfloat16* __restrict__ Bl,
    const float* __restrict__ bias, float* __restrict__ out,
    __nv_bfloat16* __restrict__ outh, __nv_bfloat16* __restrict__ outl,
    int M, int N, int K,
    const float* __restrict__ res, const float* __restrict__ extra,
    const int* __restrict__ idx) {
    extern __shared__ char sm[];
    const uint32_t smb = smem_u32(sm);
    const int tid = threadIdx.x;
    const int lane = tid & 31;
    const int w = tid >> 5;
    const int wm = w >> 1;
    const int wn = w & 1;
    const int m0 = blockIdx.y * 128;
    const int n0 = blockIdx.x * 128;

    float acc[2][8][4];
#pragma unroll
    for (int i = 0; i < 2; i++)
#pragma unroll
        for (int j = 0; j < 8; j++)
#pragma unroll
            for (int q = 0; q < 4; q++) acc[i][j][q] = 0.f;

    const int nkt = K >> 6;

    // per-thread copy coords (4 chunks per array per stage)
    int crow[4], ck8[4];
    size_t asrc[4], bsrc[4];
    uint32_t coff[4];
#pragma unroll
    for (int j = 0; j < 4; j++) {
        int c = tid + 256 * j;
        crow[j] = c >> 3;
        ck8[j] = c & 7;
        coff[j] = (uint32_t)crow[j] * 128u + (uint32_t)((ck8[j] ^ (crow[j] & 7)) << 4);
        asrc[j] = (size_t)(m0 + crow[j]) * K + ck8[j] * 8;
        bsrc[j] = (size_t)(n0 + crow[j]) * K + ck8[j] * 8;
    }

#define ISSUE_STAGE(kt)                                                        \
    do {                                                                       \
        const int kk0 = (kt) << 6;                                             \
        const uint32_t sb = smb + (uint32_t)((kt) % 3) * STG_B;                \
        _Pragma("unroll") for (int j = 0; j < 4; j++) {                        \
            cp16(sb + coff[j],           Ah + asrc[j] + kk0);                  \
            cp16(sb + 16384u + coff[j],  Al + asrc[j] + kk0);                  \
            cp16(sb + 32768u + coff[j],  Bh + bsrc[j] + kk0);                  \
            cp16(sb + 49152u + coff[j],  Bl + bsrc[j] + kk0);                  \
        }                                                                      \
        asm volatile("cp.async.commit_group;" ::: "memory");                   \
    } while (0)

    ISSUE_STAGE(0);
    ISSUE_STAGE(1);

    // ldmatrix per-thread invariants
    const uint32_t rowAb[2] = {
        (uint32_t)(wm * 32 + 0  + (lane & 7) + ((lane >> 3) & 1) * 8) * 128u,
        (uint32_t)(wm * 32 + 16 + (lane & 7) + ((lane >> 3) & 1) * 8) * 128u};
    const int a_k8add = lane >> 4;
    uint32_t rowBb[4];
#pragma unroll
    for (int nfp = 0; nfp < 4; nfp++)
        rowBb[nfp] = (uint32_t)(wn * 64 + nfp * 16 + ((lane >> 4) << 3) + (lane & 7)) * 128u;
    const int b_k8add = (lane >> 3) & 1;
    const uint32_t swz = (uint32_t)(lane & 7);

    for (int kt = 0; kt < nkt; kt++) {
        if (kt + 1 < nkt) {
            asm volatile("cp.async.wait_group 1;" ::: "memory");
        } else {
            asm volatile("cp.async.wait_group 0;" ::: "memory");
        }
        __syncthreads();
        if (kt + 2 < nkt) ISSUE_STAGE(kt + 2);

        const uint32_t sb = smb + (uint32_t)(kt % 3) * STG_B;
#pragma unroll
        for (int ks = 0; ks < 4; ks++) {
            uint32_t ah[2][4], al[2][4];
#pragma unroll
            for (int mf = 0; mf < 2; mf++) {
                uint32_t off = rowAb[mf] +
                    ((((uint32_t)(ks * 2 + a_k8add)) ^ swz) << 4);
                ldsm4(ah[mf], sb + off);
                ldsm4(al[mf], sb + 16384u + off);
            }
#pragma unroll
            for (int nfp = 0; nfp < 4; nfp++) {
                uint32_t off = rowBb[nfp] +
                    ((((uint32_t)(ks * 2 + b_k8add)) ^ swz) << 4);
                uint32_t bh[4], bl[4];
                ldsm4(bh, sb + 32768u + off);
                ldsm4(bl, sb + 49152u + off);
#pragma unroll
                for (int mf = 0; mf < 2; mf++) {
                    mma16816(acc[mf][2 * nfp],     ah[mf], bh);
                    mma16816(acc[mf][2 * nfp],     ah[mf], bl);
                    mma16816(acc[mf][2 * nfp],     al[mf], bh);
                    mma16816(acc[mf][2 * nfp + 1], ah[mf], bh + 2);
                    mma16816(acc[mf][2 * nfp + 1], ah[mf], bl + 2);
                    mma16816(acc[mf][2 * nfp + 1], al[mf], bh + 2);
                }
            }
        }
    }
#undef ISSUE_STAGE

    // epilogue
#pragma unroll
    for (int mf = 0; mf < 2; mf++) {
        int row = m0 + wm * 32 + mf * 16 + (lane >> 2);
#pragma unroll
        for (int nf = 0; nf < 8; nf++) {
            int col = n0 + wn * 64 + nf * 8 + (lane & 3) * 2;
            epi_store2<MODE>(out, outh, outl, N, row, col,
                             acc[mf][nf][0], acc[mf][nf][1], bias, res, extra, idx);
            epi_store2<MODE>(out, outh, outl, N, row + 8, col,
                             acc[mf][nf][2], acc[mf][nf][3], bias, res, extra, idx);
        }
    }
}

// ---------------- host launcher ----------------
extern "C" void kernel_launch(void* const* d_in, const int* in_sizes, int n_in,
                              void* d_out, int out_size) {
    const float* h_map   = (const float*)d_in[0];
    const float* frame   = (const float*)d_in[1];
    const int*   idx     = (const int*)  d_in[2];
    const float* Wqkv    = (const float*)d_in[3];
    const float* bqkv    = (const float*)d_in[4];
    const float* Wo      = (const float*)d_in[5];
    const float* bo      = (const float*)d_in[6];
    const float* ln1g    = (const float*)d_in[7];
    const float* ln1b    = (const float*)d_in[8];
    const float* W1      = (const float*)d_in[9];
    const float* b1      = (const float*)d_in[10];
    const float* W2      = (const float*)d_in[11];
    const float* b2      = (const float*)d_in[12];
    const float* ln2g    = (const float*)d_in[13];
    const float* ln2b    = (const float*)d_in[14];
    const float* nfg     = (const float*)d_in[15];
    const float* nfb     = (const float*)d_in[16];
    const float* patch_w = (const float*)d_in[17];
    const float* patch_b = (const float*)d_in[18];
    const float* gate_w  = (const float*)d_in[19];
    const float* gate_b  = (const float*)d_in[20];
    float* out = (float*)d_out;

    float *x, *ln, *qkv, *hcv;
    __nv_bfloat16 *lnh, *lnl, *ath, *atl, *h1h, *h1l, *cth, *ctl, *pth, *ptl, *wh, *wl;
    cudaGetSymbolAddress((void**)&x, g_x);
    cudaGetSymbolAddress((void**)&ln, g_ln);
    cudaGetSymbolAddress((void**)&qkv, g_qkv);
    cudaGetSymbolAddress((void**)&hcv, g_hcv);
    cudaGetSymbolAddress((void**)&lnh, g_lnh);
    cudaGetSymbolAddress((void**)&lnl, g_lnl);
    cudaGetSymbolAddress((void**)&ath, g_ath);
    cudaGetSymbolAddress((void**)&atl, g_atl);
    cudaGetSymbolAddress((void**)&h1h, g_h1h);
    cudaGetSymbolAddress((void**)&h1l, g_h1l);
    cudaGetSymbolAddress((void**)&cth, g_cth);
    cudaGetSymbolAddress((void**)&ctl, g_ctl);
    cudaGetSymbolAddress((void**)&pth, g_pth);
    cudaGetSymbolAddress((void**)&ptl, g_ptl);
    cudaGetSymbolAddress((void**)&wh, g_wh);
    cudaGetSymbolAddress((void**)&wl, g_wl);

    cudaFuncSetAttribute(mma_gemm_k<EPL_PLAIN>,  cudaFuncAttributeMaxDynamicSharedMemorySize, GSMEM_BYTES);
    cudaFuncSetAttribute(mma_gemm_k<EPL_RES>,    cudaFuncAttributeMaxDynamicSharedMemorySize, GSMEM_BYTES);
    cudaFuncSetAttribute(mma_gemm_k<EPL_GELU>,   cudaFuncAttributeMaxDynamicSharedMemorySize, GSMEM_BYTES);
    cudaFuncSetAttribute(mma_gemm_k<EPL_IMGTOK>, cudaFuncAttributeMaxDynamicSharedMemorySize, GSMEM_BYTES);
    cudaFuncSetAttribute(mma_gemm_k<EPL_GATE>,   cudaFuncAttributeMaxDynamicSharedMemorySize, GSMEM_BYTES);

    // pass-through copy; gated scatter overwrites idx positions
    cudaMemcpyAsync(out, h_map, sizeof(float) * (size_t)BB * WSQ * DM,
                    cudaMemcpyDeviceToDevice, 0);

    // weight conversions (once per launch)
    wcvt_k<<<1179648 / 1024, 256>>>(Wqkv,    wh + WOFF_QKV, wl + WOFF_QKV);
    wcvt_k<<<393216  / 1024, 256>>>(Wo,      wh + WOFF_WO,  wl + WOFF_WO);
    wcvt_k<<<1572864 / 1024, 256>>>(W1,      wh + WOFF_W1,  wl + WOFF_W1);
    wcvt_k<<<1572864 / 1024, 256>>>(W2,      wh + WOFF_W2,  wl + WOFF_W2);
    wcvt_k<<<196608  / 1024, 256>>>(patch_w, wh + WOFF_PW,  wl + WOFF_PW);
    wcvt_k<<<131072  / 1024, 256>>>(gate_w,  wh + WOFF_GW,  wl + WOFF_GW);

    embed_k<<<16384, 256>>>(h_map, idx, hcv, x);
    im2col_k<<<(4096 * 768) / 256, 256>>>(frame, pth, ptl);
    mma_gemm_k<EPL_IMGTOK><<<dim3(2, 32), 256, GSMEM_BYTES>>>(
        pth, ptl, wh + WOFF_PW, wl + WOFF_PW, patch_b, x, nullptr, nullptr,
        4096, 256, 768, nullptr, nullptr, nullptr);

    const int NTOK = BB * SQ;  // 20480
    for (int l = 0; l < NDEPTH; l++) {
        ln_k<false><<<NTOK / 8, 256>>>(x, nullptr, lnh, lnl,
                                       ln1g + l * 256, ln1b + l * 256);
        mma_gemm_k<EPL_PLAIN><<<dim3(6, 160), 256, GSMEM_BYTES>>>(
            lnh, lnl, wh + WOFF_QKV + (size_t)l * 196608, wl + WOFF_QKV + (size_t)l * 196608,
            bqkv + l * 768, qkv, nullptr, nullptr,
            NTOK, 768, 256, nullptr, nullptr, nullptr);
        attn_k<<<BB * NHEADS, 320>>>(qkv, ath, atl);
        mma_gemm_k<EPL_RES><<<dim3(2, 160), 256, GSMEM_BYTES>>>(
            ath, atl, wh + WOFF_WO + (size_t)l * 65536, wl + WOFF_WO + (size_t)l * 65536,
            bo + l * 256, x, nullptr, nullptr,
            NTOK, 256, 256, x, nullptr, nullptr);
        ln_k<false><<<NTOK / 8, 256>>>(x, nullptr, lnh, lnl,
                                       ln2g + l * 256, ln2b + l * 256);
        mma_gemm_k<EPL_GELU><<<dim3(8, 160), 256, GSMEM_BYTES>>>(
            lnh, lnl, wh + WOFF_W1 + (size_t)l * 262144, wl + WOFF_W1 + (size_t)l * 262144,
            b1 + l * 1024, nullptr, h1h, h1l,
            NTOK, 1024, 256, nullptr, nullptr, nullptr);
        mma_gemm_k<EPL_RES><<<dim3(2, 160), 256, GSMEM_BYTES>>>(
            h1h, h1l, wh + WOFF_W2 + (size_t)l * 262144, wl + WOFF_W2 + (size_t)l * 262144,
            b2 + l * 256, x, nullptr, nullptr,
            NTOK, 256, 1024, x, nullptr, nullptr);
    }

    ln_k<true><<<NTOK / 8, 256>>>(x, ln, lnh, lnl, nfg, nfb);
    cat_k<<<(16384 * 512) / 256, 256>>>(hcv, ln, cth, ctl);
    mma_gemm_k<EPL_GATE><<<dim3(2, 128), 256, GSMEM_BYTES>>>(
        cth, ctl, wh + WOFF_GW, wl + WOFF_GW, gate_b, out, nullptr, nullptr,
        16384, 256, 512, hcv, ln, idx);
}

// round 5
// speedup vs baseline: 3.0219x; 1.4330x over previous
#include <cuda_runtime.h>
#include <cuda_fp16.h>
#include <math.h>
#include <stdint.h>

#define BB 64
#define SQ 320
#define NCV 256
#define DM 256
#define HIDN 1024
#define NHEADS 8
#define NDEPTH 6
#define WSQ 1089

// ---------------- device scratch ----------------
__device__ float g_x[(size_t)BB * SQ * DM];
__device__ float g_ln[(size_t)BB * SQ * DM];     // final LN fp32 (gate 'extra')
__device__ float g_qkv[(size_t)BB * SQ * 3 * DM];
__device__ float g_hcv[(size_t)BB * NCV * DM];

// fp16 activation buffers
__device__ __half g_lnh[(size_t)BB * SQ * DM];
__device__ __half g_ath[(size_t)BB * SQ * DM];
__device__ __half g_h1h[(size_t)BB * SQ * HIDN];
__device__ __half g_cth[(size_t)BB * NCV * 2 * DM];
__device__ __half g_pth[(size_t)BB * 64 * 768];

// fp16 weights (one pool, fixed offsets)
#define WOFF_QKV   0u
#define WOFF_WO    1179648u
#define WOFF_W1    1572864u
#define WOFF_W2    3145728u
#define WOFF_PW    4718592u
#define WOFF_GW    4915200u
#define WPOOL_N    5046272u
__device__ __half g_wh[WPOOL_N];

// ---------------- helpers ----------------
__device__ __forceinline__ float pos2d_val(int yy, int xx, int d) {
    int dd = d & 127;
    int i = dd >> 1;
    float freq = expf((float)(2 * i) * (-0.07195578415606394f));
    float coord = (d < 128) ? (float)yy : (float)xx;
    float ang = coord * freq;
    return (d & 1) ? cosf(ang) : sinf(ang);
}

__device__ __forceinline__ float gelu_exact(float v) {
    return 0.5f * v * (1.0f + erff(v * 0.70710678118654752f));
}

// ---------------- weight fp32 -> fp16 ----------------
__global__ void __launch_bounds__(256) wcvt_k(const float* __restrict__ in,
                                              __half* __restrict__ h) {
    int i = blockIdx.x * 256 + threadIdx.x;   // one float4 per thread
    float4 v = ((const float4*)in)[i];
    __half2* hp = (__half2*)(h + (size_t)i * 4);
    hp[0] = __floats2half2_rn(v.x, v.y);
    hp[1] = __floats2half2_rn(v.z, v.w);
}

// ---------------- embed / im2col / cat ----------------
__global__ void __launch_bounds__(256) embed_k(const float* __restrict__ h_map,
                                               const int* __restrict__ idx,
                                               float* __restrict__ hcv,
                                               float* __restrict__ x) {
    int gid = blockIdx.x * 256 + threadIdx.x;
    int d = gid & 255;
    int n = (gid >> 8) & 255;
    int b = gid >> 16;
    int p = idx[n];
    float h = h_map[((size_t)b * WSQ + p) * DM + d];
    hcv[gid] = h;
    x[((size_t)(b * SQ + n)) * DM + d] = h + pos2d_val(p / 33, p % 33, d);
}

__global__ void __launch_bounds__(256) im2col_k(const float* __restrict__ frame,
                                                __half* __restrict__ ph) {
    int gid = blockIdx.x * 256 + threadIdx.x;   // < 4096*768
    int k = gid % 768;
    int m = gid / 768;
    int c = k >> 8;
    int r = (k >> 4) & 15;
    int q = k & 15;
    int t = m & 63, b = m >> 6;
    int yy = (t >> 3) * 16 + r;
    int xx = (t & 7) * 16 + q;
    ph[gid] = __float2half_rn(frame[(((size_t)b * 3 + c) * 128 + yy) * 128 + xx]);
}

__global__ void __launch_bounds__(256) cat_k(const float* __restrict__ hcv,
                                             const float* __restrict__ lnx,
                                             __half* __restrict__ ch) {
    int gid = blockIdx.x * 256 + threadIdx.x;   // < 16384*512
    int dcol = gid & 511;
    int m = gid >> 9;
    int b = m >> 8, n = m & 255;
    float v = (dcol < 256) ? hcv[((size_t)m << 8) + dcol]
                           : lnx[(((size_t)(b * SQ + n)) << 8) + (dcol - 256)];
    ch[gid] = __float2half_rn(v);
}

// ---------------- LayerNorm: emits fp16 (+optional fp32) ----------------
template <bool F32OUT>
__global__ void __launch_bounds__(256) ln_k(const float* __restrict__ x,
                                            float* __restrict__ y,
                                            __half* __restrict__ yh,
                                            const float* __restrict__ gam,
                                            const float* __restrict__ bet) {
    int warp = threadIdx.x >> 5;
    int lane = threadIdx.x & 31;
    int tok = blockIdx.x * 8 + warp;
    const float* xp = x + (size_t)tok * DM;
    float v[8];
    float sum = 0.f, sq = 0.f;
#pragma unroll
    for (int i = 0; i < 8; i++) {
        v[i] = xp[lane + 32 * i];
        sum += v[i];
        sq += v[i] * v[i];
    }
#pragma unroll
    for (int off = 16; off; off >>= 1) {
        sum += __shfl_xor_sync(0xffffffffu, sum, off);
        sq  += __shfl_xor_sync(0xffffffffu, sq, off);
    }
    float mu = sum * (1.0f / 256.0f);
    float var = sq * (1.0f / 256.0f) - mu * mu;
    float inv = rsqrtf(var + 1e-5f);
#pragma unroll
    for (int i = 0; i < 8; i++) {
        int d = lane + 32 * i;
        float r = (v[i] - mu) * inv * gam[d] + bet[d];
        if (F32OUT) y[(size_t)tok * DM + d] = r;
        yh[(size_t)tok * DM + d] = __float2half_rn(r);
    }
}

// ---------------- attention (emits fp16) ----------------
__global__ void __launch_bounds__(320) attn_k(const float* __restrict__ qkv,
                                              __half* __restrict__ oh) {
    __shared__ float Ks[160 * 32];
    __shared__ float Vs[160 * 32];
    int b = blockIdx.x >> 3;
    int h = blockIdx.x & 7;
    int tid = threadIdx.x;
    const float* base = qkv + (size_t)b * SQ * 768;

    float q[32];
    const float* qp = base + (size_t)tid * 768 + h * 32;
    const float scale = 0.17677669529663687f;
#pragma unroll
    for (int d = 0; d < 32; d += 4) {
        float4 t = *(const float4*)(qp + d);
        q[d] = t.x * scale; q[d + 1] = t.y * scale; q[d + 2] = t.z * scale; q[d + 3] = t.w * scale;
    }

    float m = -1e30f, l = 0.f;
    float o[32];
#pragma unroll
    for (int d = 0; d < 32; d++) o[d] = 0.f;

    int row = tid >> 1;
    int part = (tid & 1) * 16;

    for (int c = 0; c < 2; c++) {
        __syncthreads();
        const float* kp = base + (size_t)(c * 160 + row) * 768 + 256 + h * 32 + part;
#pragma unroll
        for (int j = 0; j < 4; j++) {
            *(float4*)&Ks[row * 32 + part + j * 4] = *(const float4*)(kp + j * 4);
            *(float4*)&Vs[row * 32 + part + j * 4] = *(const float4*)(kp + 256 + j * 4);
        }
        __syncthreads();

        for (int key = 0; key < 160; key++) {
            const float* kr = &Ks[key * 32];
            float s = 0.f;
#pragma unroll
            for (int d = 0; d < 32; d++) s += q[d] * kr[d];
            float nm = fmaxf(m, s);
            float corr = __expf(m - nm);
            float p = __expf(s - nm);
            l = l * corr + p;
            const float* vr = &Vs[key * 32];
#pragma unroll
            for (int d = 0; d < 32; d++) o[d] = o[d] * corr + p * vr[d];
            m = nm;
        }
    }
    float inv = 1.f / l;
    size_t obase = ((size_t)(b * SQ + tid)) * DM + h * 32;
#pragma unroll
    for (int d = 0; d < 32; d += 2) {
        *(__half2*)(oh + obase + d) = __floats2half2_rn(o[d] * inv, o[d + 1] * inv);
    }
}

// ================= HMMA fp16 pipelined GEMM =================
// C[M,N] = A @ W^T + bias (+epilogue). A,W fp16 K-major.
// CTA 128x128, BK=64, 256 thr (8 warps 4x2, warp 32x64), 3-stage cp.async.
enum { EPL_PLAIN = 0, EPL_RES = 1, EPL_GELU = 2, EPL_IMGTOK = 3, EPL_GATE = 4 };

#define STG_B 32768u      // per-stage smem: A | B, 16KB each
#define GSMEM_BYTES (3u * STG_B)

__device__ __forceinline__ uint32_t smem_u32(const void* p) {
    uint32_t a;
    asm("{ .reg .u64 t; cvta.to.shared.u64 t, %1; cvt.u32.u64 %0, t; }" : "=r"(a) : "l"(p));
    return a;
}

__device__ __forceinline__ void cp16(uint32_t dst, const void* src) {
    asm volatile("cp.async.cg.shared.global [%0], [%1], 16;" :: "r"(dst), "l"(src));
}

__device__ __forceinline__ void ldsm4(uint32_t* r, uint32_t addr) {
    asm volatile("ldmatrix.sync.aligned.m8n8.x4.shared.b16 {%0,%1,%2,%3}, [%4];"
                 : "=r"(r[0]), "=r"(r[1]), "=r"(r[2]), "=r"(r[3]) : "r"(addr));
}

__device__ __forceinline__ void mma16816(float* c, const uint32_t* a, const uint32_t* b) {
    asm volatile(
        "mma.sync.aligned.m16n8k16.row.col.f32.f16.f16.f32 "
        "{%0,%1,%2,%3}, {%4,%5,%6,%7}, {%8,%9}, {%0,%1,%2,%3};\n"
        : "+f"(c[0]), "+f"(c[1]), "+f"(c[2]), "+f"(c[3])
        : "r"(a[0]), "r"(a[1]), "r"(a[2]), "r"(a[3]), "r"(b[0]), "r"(b[1]));
}

template <int MODE>
__device__ __forceinline__ void epi_store2(
    float* __restrict__ out, __half* __restrict__ outh,
    int N, int row, int col, float vx, float vy,
    const float* __restrict__ bias, const float* __restrict__ res,
    const float* __restrict__ extra, const int* __restrict__ idx) {
    float2 bb = *(const float2*)(bias + col);
    vx += bb.x;
    vy += bb.y;
    if (MODE == EPL_PLAIN) {
        *(float2*)&out[(size_t)row * N + col] = make_float2(vx, vy);
    } else if (MODE == EPL_RES) {
        float2 rr = *(const float2*)&res[(size_t)row * N + col];
        *(float2*)&out[(size_t)row * N + col] = make_float2(vx + rr.x, vy + rr.y);
    } else if (MODE == EPL_GELU) {
        *(__half2*)&outh[(size_t)row * N + col] =
            __floats2half2_rn(gelu_exact(vx), gelu_exact(vy));
    } else if (MODE == EPL_IMGTOK) {
        int b = row >> 6, tt = row & 63;
        int yy = tt >> 3, xx = tt & 7;
        vx += pos2d_val(yy, xx, col);
        vy += pos2d_val(yy, xx, col + 1);
        *(float2*)&out[((size_t)(b * SQ + NCV + tt)) * DM + col] = make_float2(vx, vy);
    } else {  // EPL_GATE
        int b = row >> 8, n = row & 255;
        int p = idx[n];
        float2 hc = *(const float2*)&res[(size_t)row * DM + col];
        float2 hn = *(const float2*)&extra[((size_t)(b * SQ + n)) * DM + col];
        float g0 = 1.f / (1.f + expf(-vx));
        float g1 = 1.f / (1.f + expf(-vy));
        float2 r;
        r.x = hc.x + g0 * (hn.x - hc.x);
        r.y = hc.y + g1 * (hn.y - hc.y);
        *(float2*)&out[((size_t)b * WSQ + p) * DM + col] = r;
    }
}

template <int MODE>
__global__ void __launch_bounds__(256) mma_gemm_k(
    const __half* __restrict__ Ah, const __half* __restrict__ Bh,
    const float* __restrict__ bias, float* __restrict__ out,
    __half* __restrict__ outh,
    int M, int N, int K,
    const float* __restrict__ res, const float* __restrict__ extra,
    const int* __restrict__ idx) {
    extern __shared__ char sm[];
    const uint32_t smb = smem_u32(sm);
    const int tid = threadIdx.x;
    const int lane = tid & 31;
    const int w = tid >> 5;
    const int wm = w >> 1;
    const int wn = w & 1;
    const int m0 = blockIdx.y * 128;
    const int n0 = blockIdx.x * 128;

    float acc[2][8][4];
#pragma unroll
    for (int i = 0; i < 2; i++)
#pragma unroll
        for (int j = 0; j < 8; j++)
#pragma unroll
            for (int q = 0; q < 4; q++) acc[i][j][q] = 0.f;

    const int nkt = K >> 6;

    // per-thread copy coords (4 x 16B chunks per array per stage)
    int crow[4], ck8[4];
    size_t asrc[4], bsrc[4];
    uint32_t coff[4];
#pragma unroll
    for (int j = 0; j < 4; j++) {
        int c = tid + 256 * j;
        crow[j] = c >> 3;
        ck8[j] = c & 7;
        coff[j] = (uint32_t)crow[j] * 128u + (uint32_t)((ck8[j] ^ (crow[j] & 7)) << 4);
        asrc[j] = (size_t)(m0 + crow[j]) * K + ck8[j] * 8;
        bsrc[j] = (size_t)(n0 + crow[j]) * K + ck8[j] * 8;
    }

#define ISSUE_STAGE(kt)                                                        \
    do {                                                                       \
        const int kk0 = (kt) << 6;                                             \
        const uint32_t sb = smb + (uint32_t)((kt) % 3) * STG_B;                \
        _Pragma("unroll") for (int j = 0; j < 4; j++) {                        \
            cp16(sb + coff[j],          Ah + asrc[j] + kk0);                   \
            cp16(sb + 16384u + coff[j], Bh + bsrc[j] + kk0);                   \
        }                                                                      \
        asm volatile("cp.async.commit_group;" ::: "memory");                   \
    } while (0)

    ISSUE_STAGE(0);
    ISSUE_STAGE(1);

    // ldmatrix per-thread invariants
    const uint32_t rowAb[2] = {
        (uint32_t)(wm * 32 + 0  + (lane & 7) + ((lane >> 3) & 1) * 8) * 128u,
        (uint32_t)(wm * 32 + 16 + (lane & 7) + ((lane >> 3) & 1) * 8) * 128u};
    const int a_k8add = lane >> 4;
    uint32_t rowBb[4];
#pragma unroll
    for (int nfp = 0; nfp < 4; nfp++)
        rowBb[nfp] = (uint32_t)(wn * 64 + nfp * 16 + ((lane >> 4) << 3) + (lane & 7)) * 128u;
    const int b_k8add = (lane >> 3) & 1;
    const uint32_t swz = (uint32_t)(lane & 7);

    for (int kt = 0; kt < nkt; kt++) {
        if (kt + 1 < nkt) {
            asm volatile("cp.async.wait_group 1;" ::: "memory");
        } else {
            asm volatile("cp.async.wait_group 0;" ::: "memory");
        }
        __syncthreads();
        if (kt + 2 < nkt) ISSUE_STAGE(kt + 2);

        const uint32_t sb = smb + (uint32_t)(kt % 3) * STG_B;
#pragma unroll
        for (int ks = 0; ks < 4; ks++) {
            uint32_t ah[2][4];
#pragma unroll
            for (int mf = 0; mf < 2; mf++) {
                uint32_t off = rowAb[mf] +
                    ((((uint32_t)(ks * 2 + a_k8add)) ^ swz) << 4);
                ldsm4(ah[mf], sb + off);
            }
#pragma unroll
            for (int nfp = 0; nfp < 4; nfp++) {
                uint32_t off = rowBb[nfp] +
                    ((((uint32_t)(ks * 2 + b_k8add)) ^ swz) << 4);
                uint32_t bh[4];
                ldsm4(bh, sb + 16384u + off);
#pragma unroll
                for (int mf = 0; mf < 2; mf++) {
                    mma16816(acc[mf][2 * nfp],     ah[mf], bh);
                    mma16816(acc[mf][2 * nfp + 1], ah[mf], bh + 2);
                }
            }
        }
    }
#undef ISSUE_STAGE

    // epilogue
#pragma unroll
    for (int mf = 0; mf < 2; mf++) {
        int row = m0 + wm * 32 + mf * 16 + (lane >> 2);
#pragma unroll
        for (int nf = 0; nf < 8; nf++) {
            int col = n0 + wn * 64 + nf * 8 + (lane & 3) * 2;
            epi_store2<MODE>(out, outh, N, row, col,
                             acc[mf][nf][0], acc[mf][nf][1], bias, res, extra, idx);
            epi_store2<MODE>(out, outh, N, row + 8, col,
                             acc[mf][nf][2], acc[mf][nf][3], bias, res, extra, idx);
        }
    }
}

// ---------------- host launcher ----------------
extern "C" void kernel_launch(void* const* d_in, const int* in_sizes, int n_in,
                              void* d_out, int out_size) {
    const float* h_map   = (const float*)d_in[0];
    const float* frame   = (const float*)d_in[1];
    const int*   idx     = (const int*)  d_in[2];
    const float* Wqkv    = (const float*)d_in[3];
    const float* bqkv    = (const float*)d_in[4];
    const float* Wo      = (const float*)d_in[5];
    const float* bo      = (const float*)d_in[6];
    const float* ln1g    = (const float*)d_in[7];
    const float* ln1b    = (const float*)d_in[8];
    const float* W1      = (const float*)d_in[9];
    const float* b1      = (const float*)d_in[10];
    const float* W2      = (const float*)d_in[11];
    const float* b2      = (const float*)d_in[12];
    const float* ln2g    = (const float*)d_in[13];
    const float* ln2b    = (const float*)d_in[14];
    const float* nfg     = (const float*)d_in[15];
    const float* nfb     = (const float*)d_in[16];
    const float* patch_w = (const float*)d_in[17];
    const float* patch_b = (const float*)d_in[18];
    const float* gate_w  = (const float*)d_in[19];
    const float* gate_b  = (const float*)d_in[20];
    float* out = (float*)d_out;

    float *x, *ln, *qkv, *hcv;
    __half *lnh, *ath, *h1h, *cth, *pth, *wh;
    cudaGetSymbolAddress((void**)&x, g_x);
    cudaGetSymbolAddress((void**)&ln, g_ln);
    cudaGetSymbolAddress((void**)&qkv, g_qkv);
    cudaGetSymbolAddress((void**)&hcv, g_hcv);
    cudaGetSymbolAddress((void**)&lnh, g_lnh);
    cudaGetSymbolAddress((void**)&ath, g_ath);
    cudaGetSymbolAddress((void**)&h1h, g_h1h);
    cudaGetSymbolAddress((void**)&cth, g_cth);
    cudaGetSymbolAddress((void**)&pth, g_pth);
    cudaGetSymbolAddress((void**)&wh, g_wh);

    cudaFuncSetAttribute(mma_gemm_k<EPL_PLAIN>,  cudaFuncAttributeMaxDynamicSharedMemorySize, GSMEM_BYTES);
    cudaFuncSetAttribute(mma_gemm_k<EPL_RES>,    cudaFuncAttributeMaxDynamicSharedMemorySize, GSMEM_BYTES);
    cudaFuncSetAttribute(mma_gemm_k<EPL_GELU>,   cudaFuncAttributeMaxDynamicSharedMemorySize, GSMEM_BYTES);
    cudaFuncSetAttribute(mma_gemm_k<EPL_IMGTOK>, cudaFuncAttributeMaxDynamicSharedMemorySize, GSMEM_BYTES);
    cudaFuncSetAttribute(mma_gemm_k<EPL_GATE>,   cudaFuncAttributeMaxDynamicSharedMemorySize, GSMEM_BYTES);

    // pass-through copy; gated scatter overwrites idx positions
    cudaMemcpyAsync(out, h_map, sizeof(float) * (size_t)BB * WSQ * DM,
                    cudaMemcpyDeviceToDevice, 0);

    // weight conversions (once per launch)
    wcvt_k<<<1179648 / 1024, 256>>>(Wqkv,    wh + WOFF_QKV);
    wcvt_k<<<393216  / 1024, 256>>>(Wo,      wh + WOFF_WO);
    wcvt_k<<<1572864 / 1024, 256>>>(W1,      wh + WOFF_W1);
    wcvt_k<<<1572864 / 1024, 256>>>(W2,      wh + WOFF_W2);
    wcvt_k<<<196608  / 1024, 256>>>(patch_w, wh + WOFF_PW);
    wcvt_k<<<131072  / 1024, 256>>>(gate_w,  wh + WOFF_GW);

    embed_k<<<16384, 256>>>(h_map, idx, hcv, x);
    im2col_k<<<(4096 * 768) / 256, 256>>>(frame, pth);
    mma_gemm_k<EPL_IMGTOK><<<dim3(2, 32), 256, GSMEM_BYTES>>>(
        pth, wh + WOFF_PW, patch_b, x, nullptr,
        4096, 256, 768, nullptr, nullptr, nullptr);

    const int NTOK = BB * SQ;  // 20480
    for (int l = 0; l < NDEPTH; l++) {
        ln_k<false><<<NTOK / 8, 256>>>(x, nullptr, lnh,
                                       ln1g + l * 256, ln1b + l * 256);
        mma_gemm_k<EPL_PLAIN><<<dim3(6, 160), 256, GSMEM_BYTES>>>(
            lnh, wh + WOFF_QKV + (size_t)l * 196608,
            bqkv + l * 768, qkv, nullptr,
            NTOK, 768, 256, nullptr, nullptr, nullptr);
        attn_k<<<BB * NHEADS, 320>>>(qkv, ath);
        mma_gemm_k<EPL_RES><<<dim3(2, 160), 256, GSMEM_BYTES>>>(
            ath, wh + WOFF_WO + (size_t)l * 65536,
            bo + l * 256, x, nullptr,
            NTOK, 256, 256, x, nullptr, nullptr);
        ln_k<false><<<NTOK / 8, 256>>>(x, nullptr, lnh,
                                       ln2g + l * 256, ln2b + l * 256);
        mma_gemm_k<EPL_GELU><<<dim3(8, 160), 256, GSMEM_BYTES>>>(
            lnh, wh + WOFF_W1 + (size_t)l * 262144,
            b1 + l * 1024, nullptr, h1h,
            NTOK, 1024, 256, nullptr, nullptr, nullptr);
        mma_gemm_k<EPL_RES><<<dim3(2, 160), 256, GSMEM_BYTES>>>(
            h1h, wh + WOFF_W2 + (size_t)l * 262144,
            b2 + l * 256, x, nullptr,
            NTOK, 256, 1024, x, nullptr, nullptr);
    }

    ln_k<true><<<NTOK / 8, 256>>>(x, ln, lnh, nfg, nfb);
    cat_k<<<(16384 * 512) / 256, 256>>>(hcv, ln, cth);
    mma_gemm_k<EPL_GATE><<<dim3(2, 128), 256, GSMEM_BYTES>>>(
        cth, wh + WOFF_GW, gate_b, out, nullptr,
        16384, 256, 512, hcv, ln, idx);
}

// round 7
// speedup vs baseline: 6.2819x; 2.0788x over previous
#include <cuda_runtime.h>
#include <cuda_fp16.h>
#include <math.h>
#include <stdint.h>

#define BB 64
#define SQ 320
#define NCV 256
#define DM 256
#define HIDN 1024
#define NHEADS 8
#define NDEPTH 6
#define WSQ 1089

// ---------------- device scratch ----------------
__device__ float g_x[(size_t)BB * SQ * DM];
__device__ float g_ln[(size_t)BB * SQ * DM];     // final LN fp32 (gate 'extra')
__device__ float g_hcv[(size_t)BB * NCV * DM];

// fp16 activation buffers
__device__ __half g_lnh[(size_t)BB * SQ * DM];
__device__ __half g_qkvh[(size_t)BB * SQ * 3 * DM];
__device__ __half g_ath[(size_t)BB * SQ * DM];
__device__ __half g_h1h[(size_t)BB * SQ * HIDN];
__device__ __half g_cth[(size_t)BB * NCV * 2 * DM];
__device__ __half g_pth[(size_t)BB * 64 * 768];

// fp16 weights (one pool, fixed offsets)
#define WOFF_QKV   0u
#define WOFF_WO    1179648u
#define WOFF_W1    1572864u
#define WOFF_W2    3145728u
#define WOFF_PW    4718592u
#define WOFF_GW    4915200u
#define WPOOL_N    5046272u
__device__ __half g_wh[WPOOL_N];

// ---------------- helpers ----------------
__device__ __forceinline__ float pos2d_val(int yy, int xx, int d) {
    int dd = d & 127;
    int i = dd >> 1;
    float freq = expf((float)(2 * i) * (-0.07195578415606394f));
    float coord = (d < 128) ? (float)yy : (float)xx;
    float ang = coord * freq;
    return (d & 1) ? cosf(ang) : sinf(ang);
}

__device__ __forceinline__ float gelu_exact(float v) {
    return 0.5f * v * (1.0f + erff(v * 0.70710678118654752f));
}

__device__ __forceinline__ uint32_t smem_u32(const void* p) {
    uint32_t a;
    asm("{ .reg .u64 t; cvta.to.shared.u64 t, %1; cvt.u32.u64 %0, t; }" : "=r"(a) : "l"(p));
    return a;
}

__device__ __forceinline__ void cp16(uint32_t dst, const void* src) {
    asm volatile("cp.async.cg.shared.global [%0], [%1], 16;" :: "r"(dst), "l"(src));
}

__device__ __forceinline__ void ldsm4(uint32_t* r, uint32_t addr) {
    asm volatile("ldmatrix.sync.aligned.m8n8.x4.shared.b16 {%0,%1,%2,%3}, [%4];"
                 : "=r"(r[0]), "=r"(r[1]), "=r"(r[2]), "=r"(r[3]) : "r"(addr));
}

__device__ __forceinline__ void ldsm4t(uint32_t* r, uint32_t addr) {
    asm volatile("ldmatrix.sync.aligned.m8n8.x4.trans.shared.b16 {%0,%1,%2,%3}, [%4];"
                 : "=r"(r[0]), "=r"(r[1]), "=r"(r[2]), "=r"(r[3]) : "r"(addr));
}

__device__ __forceinline__ void mma16816(float* c, const uint32_t* a, const uint32_t* b) {
    asm volatile(
        "mma.sync.aligned.m16n8k16.row.col.f32.f16.f16.f32 "
        "{%0,%1,%2,%3}, {%4,%5,%6,%7}, {%8,%9}, {%0,%1,%2,%3};\n"
        : "+f"(c[0]), "+f"(c[1]), "+f"(c[2]), "+f"(c[3])
        : "r"(a[0]), "r"(a[1]), "r"(a[2]), "r"(a[3]), "r"(b[0]), "r"(b[1]));
}

// ---------------- weight fp32 -> fp16 ----------------
__global__ void __launch_bounds__(256) wcvt_k(const float* __restrict__ in,
                                              __half* __restrict__ h) {
    int i = blockIdx.x * 256 + threadIdx.x;
    float4 v = ((const float4*)in)[i];
    __half2* hp = (__half2*)(h + (size_t)i * 4);
    hp[0] = __floats2half2_rn(v.x, v.y);
    hp[1] = __floats2half2_rn(v.z, v.w);
}

// ---------------- embed / im2col / cat ----------------
__global__ void __launch_bounds__(256) embed_k(const float* __restrict__ h_map,
                                               const int* __restrict__ idx,
                                               float* __restrict__ hcv,
                                               float* __restrict__ x) {
    int gid = blockIdx.x * 256 + threadIdx.x;
    int d = gid & 255;
    int n = (gid >> 8) & 255;
    int b = gid >> 16;
    int p = idx[n];
    float h = h_map[((size_t)b * WSQ + p) * DM + d];
    hcv[gid] = h;
    x[((size_t)(b * SQ + n)) * DM + d] = h + pos2d_val(p / 33, p % 33, d);
}

__global__ void __launch_bounds__(256) im2col_k(const float* __restrict__ frame,
                                                __half* __restrict__ ph) {
    int gid = blockIdx.x * 256 + threadIdx.x;
    int k = gid % 768;
    int m = gid / 768;
    int c = k >> 8;
    int r = (k >> 4) & 15;
    int q = k & 15;
    int t = m & 63, b = m >> 6;
    int yy = (t >> 3) * 16 + r;
    int xx = (t & 7) * 16 + q;
    ph[gid] = __float2half_rn(frame[(((size_t)b * 3 + c) * 128 + yy) * 128 + xx]);
}

__global__ void __launch_bounds__(256) cat_k(const float* __restrict__ hcv,
                                             const float* __restrict__ lnx,
                                             __half* __restrict__ ch) {
    int gid = blockIdx.x * 256 + threadIdx.x;
    int dcol = gid & 511;
    int m = gid >> 9;
    int b = m >> 8, n = m & 255;
    float v = (dcol < 256) ? hcv[((size_t)m << 8) + dcol]
                           : lnx[(((size_t)(b * SQ + n)) << 8) + (dcol - 256)];
    ch[gid] = __float2half_rn(v);
}

// ---------------- LayerNorm: emits fp16 (+optional fp32) ----------------
template <bool F32OUT>
__global__ void __launch_bounds__(256) ln_k(const float* __restrict__ x,
                                            float* __restrict__ y,
                                            __half* __restrict__ yh,
                                            const float* __restrict__ gam,
                                            const float* __restrict__ bet) {
    int warp = threadIdx.x >> 5;
    int lane = threadIdx.x & 31;
    int tok = blockIdx.x * 8 + warp;
    const float* xp = x + (size_t)tok * DM;
    float v[8];
    float sum = 0.f, sq = 0.f;
#pragma unroll
    for (int i = 0; i < 8; i++) {
        v[i] = xp[lane + 32 * i];
        sum += v[i];
        sq += v[i] * v[i];
    }
#pragma unroll
    for (int off = 16; off; off >>= 1) {
        sum += __shfl_xor_sync(0xffffffffu, sum, off);
        sq  += __shfl_xor_sync(0xffffffffu, sq, off);
    }
    float mu = sum * (1.0f / 256.0f);
    float var = sq * (1.0f / 256.0f) - mu * mu;
    float inv = rsqrtf(var + 1e-5f);
#pragma unroll
    for (int i = 0; i < 8; i++) {
        int d = lane + 32 * i;
        float r = (v[i] - mu) * inv * gam[d] + bet[d];
        if (F32OUT) y[(size_t)tok * DM + d] = r;
        yh[(size_t)tok * DM + d] = __float2half_rn(r);
    }
}

// ================= fused flash attention (mma.sync fp16) =================
// Grid: B*NHEADS CTAs. Block: 320 thr (10 warps; warp w = queries w*32..w*32+31).
// qkvh: [B,320,768] fp16, q pre-scaled by 1/sqrt(32). K chunks of 64, online softmax.
#define ATT_RS 80u                      // padded row stride bytes (32 halves -> 40)
#define ATT_TEN (320u * ATT_RS)         // 25600 per tensor
#define ATT_SMEM (3u * ATT_TEN)         // 76800

__global__ void __launch_bounds__(320) attn_fa_k(const __half* __restrict__ qkvh,
                                                 __half* __restrict__ oh) {
    extern __shared__ char sm[];
    const uint32_t smb = smem_u32(sm);
    const int b = blockIdx.x >> 3;
    const int h = blockIdx.x & 7;
    const int tid = threadIdx.x;
    const int l = tid & 31;
    const int w = tid >> 5;

    // ---- stage Q,K,V into smem (fp16, stride 80B) ----
    // 3 tensors x 320 rows x 4 chunks(16B) = 3840 chunks; 1280 chunks per tensor
#pragma unroll
    for (int j = 0; j < 12; j++) {
        int c = j * 320 + tid;          // 0..3839
        int tz = c / 1280;              // tensor 0,1,2
        int rem = c - tz * 1280;
        int r = rem >> 2;               // row 0..319
        int ch = rem & 3;               // 16B chunk
        const __half* src = qkvh + (size_t)(b * SQ + r) * 768 + tz * 256 + h * 32 + ch * 8;
        cp16(smb + (uint32_t)tz * ATT_TEN + (uint32_t)r * ATT_RS + (uint32_t)ch * 16u, src);
    }
    asm volatile("cp.async.commit_group;" ::: "memory");
    asm volatile("cp.async.wait_group 0;" ::: "memory");
    __syncthreads();

    const uint32_t smQ = smb, smK = smb + ATT_TEN, smV = smb + 2 * ATT_TEN;
    const int q0 = w * 32;

    // Q a-frags: aq[mf][kc][4]
    uint32_t aq[2][2][4];
#pragma unroll
    for (int mf = 0; mf < 2; mf++)
#pragma unroll
        for (int kc = 0; kc < 2; kc++) {
            uint32_t addr = smQ +
                (uint32_t)(q0 + mf * 16 + (l & 7) + ((l >> 3) & 1) * 8) * ATT_RS +
                (uint32_t)(kc * 2 + (l >> 4)) * 16u;
            ldsm4(aq[mf][kc], addr);
        }

    float mrow[2][2] = {{-1e30f, -1e30f}, {-1e30f, -1e30f}};
    float lrow[2][2] = {{0.f, 0.f}, {0.f, 0.f}};
    float acc_o[2][4][4];
#pragma unroll
    for (int mf = 0; mf < 2; mf++)
#pragma unroll
        for (int db = 0; db < 4; db++)
#pragma unroll
            for (int q = 0; q < 4; q++) acc_o[mf][db][q] = 0.f;

    for (int ck = 0; ck < 320; ck += 64) {
        // ---- scores S = Q @ K^T (m32 x n64, k=32) ----
        float s[2][8][4];
#pragma unroll
        for (int mf = 0; mf < 2; mf++)
#pragma unroll
            for (int nb = 0; nb < 8; nb++)
#pragma unroll
                for (int q = 0; q < 4; q++) s[mf][nb][q] = 0.f;

#pragma unroll
        for (int g = 0; g < 4; g++) {
#pragma unroll
            for (int ks = 0; ks < 2; ks++) {
                uint32_t bk[4];
                uint32_t addr = smK +
                    (uint32_t)(ck + g * 16 + ((l >> 4) << 3) + (l & 7)) * ATT_RS +
                    (uint32_t)(ks * 2 + ((l >> 3) & 1)) * 16u;
                ldsm4(bk, addr);
#pragma unroll
                for (int mf = 0; mf < 2; mf++) {
                    mma16816(s[mf][2 * g],     aq[mf][ks], bk);
                    mma16816(s[mf][2 * g + 1], aq[mf][ks], bk + 2);
                }
            }
        }

        // ---- online softmax (rows: l>>2 and l>>2 + 8 per mf) ----
        uint32_t ap[2][4][4];   // P a-frags
#pragma unroll
        for (int mf = 0; mf < 2; mf++) {
#pragma unroll
            for (int hh = 0; hh < 2; hh++) {
                float mx = -1e30f;
#pragma unroll
                for (int nb = 0; nb < 8; nb++) {
                    mx = fmaxf(mx, fmaxf(s[mf][nb][hh * 2], s[mf][nb][hh * 2 + 1]));
                }
                mx = fmaxf(mx, __shfl_xor_sync(0xffffffffu, mx, 1));
                mx = fmaxf(mx, __shfl_xor_sync(0xffffffffu, mx, 2));
                float mnew = fmaxf(mrow[mf][hh], mx);
                float corr = __expf(mrow[mf][hh] - mnew);
                mrow[mf][hh] = mnew;
                float lsum = 0.f;
#pragma unroll
                for (int nb = 0; nb < 8; nb++) {
                    float p0 = __expf(s[mf][nb][hh * 2]     - mnew);
                    float p1 = __expf(s[mf][nb][hh * 2 + 1] - mnew);
                    s[mf][nb][hh * 2] = p0;
                    s[mf][nb][hh * 2 + 1] = p1;
                    lsum += p0 + p1;
                }
                lsum += __shfl_xor_sync(0xffffffffu, lsum, 1);
                lsum += __shfl_xor_sync(0xffffffffu, lsum, 2);
                lrow[mf][hh] = lrow[mf][hh] * corr + lsum;
#pragma unroll
                for (int db = 0; db < 4; db++) {
                    acc_o[mf][db][hh * 2]     *= corr;
                    acc_o[mf][db][hh * 2 + 1] *= corr;
                }
            }
            // pack P to fp16 a-frags: ap[mf][g] over k16 = keys 16g..16g+15
#pragma unroll
            for (int g = 0; g < 4; g++) {
                __half2 h0 = __floats2half2_rn(s[mf][2 * g][0],     s[mf][2 * g][1]);
                __half2 h1 = __floats2half2_rn(s[mf][2 * g][2],     s[mf][2 * g][3]);
                __half2 h2 = __floats2half2_rn(s[mf][2 * g + 1][0], s[mf][2 * g + 1][1]);
                __half2 h3 = __floats2half2_rn(s[mf][2 * g + 1][2], s[mf][2 * g + 1][3]);
                ap[mf][g][0] = *(uint32_t*)&h0;
                ap[mf][g][1] = *(uint32_t*)&h1;
                ap[mf][g][2] = *(uint32_t*)&h2;
                ap[mf][g][3] = *(uint32_t*)&h3;
            }
        }

        // ---- O += P @ V (k = 64 keys, n = 32 dims) ----
#pragma unroll
        for (int g = 0; g < 4; g++) {
#pragma unroll
            for (int dd = 0; dd < 2; dd++) {
                uint32_t bv[4];
                uint32_t addr = smV +
                    (uint32_t)(ck + g * 16 + ((l >> 3) & 1) * 8 + (l & 7)) * ATT_RS +
                    (uint32_t)(dd * 2 + (l >> 4)) * 16u;
                ldsm4t(bv, addr);
#pragma unroll
                for (int mf = 0; mf < 2; mf++) {
                    mma16816(acc_o[mf][dd * 2],     ap[mf][g], bv);
                    mma16816(acc_o[mf][dd * 2 + 1], ap[mf][g], bv + 2);
                }
            }
        }
    }

    // ---- finalize: O /= l, write fp16 ----
#pragma unroll
    for (int mf = 0; mf < 2; mf++) {
#pragma unroll
        for (int hh = 0; hh < 2; hh++) {
            float inv = 1.f / lrow[mf][hh];
            int tok = q0 + mf * 16 + (l >> 2) + hh * 8;
            __half* op = oh + (size_t)(b * SQ + tok) * DM + h * 32 + 2 * (l & 3);
#pragma unroll
            for (int db = 0; db < 4; db++) {
                __half2 r = __floats2half2_rn(acc_o[mf][db][hh * 2] * inv,
                                              acc_o[mf][db][hh * 2 + 1] * inv);
                *(__half2*)(op + db * 8) = r;
            }
        }
    }
}

// ================= HMMA fp16 pipelined GEMM =================
enum { EPL_PLAIN = 0, EPL_RES = 1, EPL_GELU = 2, EPL_IMGTOK = 3, EPL_GATE = 4, EPL_QKVH = 5 };

#define STG_B 32768u
#define GSMEM_BYTES (3u * STG_B)

template <int MODE>
__device__ __forceinline__ void epi_store2(
    float* __restrict__ out, __half* __restrict__ outh,
    int N, int row, int col, float vx, float vy,
    const float* __restrict__ bias, const float* __restrict__ res,
    const float* __restrict__ extra, const int* __restrict__ idx) {
    float2 bb = *(const float2*)(bias + col);
    vx += bb.x;
    vy += bb.y;
    if (MODE == EPL_PLAIN) {
        *(float2*)&out[(size_t)row * N + col] = make_float2(vx, vy);
    } else if (MODE == EPL_RES) {
        float2 rr = *(const float2*)&res[(size_t)row * N + col];
        *(float2*)&out[(size_t)row * N + col] = make_float2(vx + rr.x, vy + rr.y);
    } else if (MODE == EPL_GELU) {
        *(__half2*)&outh[(size_t)row * N + col] =
            __floats2half2_rn(gelu_exact(vx), gelu_exact(vy));
    } else if (MODE == EPL_QKVH) {
        float sc = (col < 256) ? 0.17677669529663687f : 1.0f;
        *(__half2*)&outh[(size_t)row * N + col] = __floats2half2_rn(vx * sc, vy * sc);
    } else if (MODE == EPL_IMGTOK) {
        int b = row >> 6, tt = row & 63;
        int yy = tt >> 3, xx = tt & 7;
        vx += pos2d_val(yy, xx, col);
        vy += pos2d_val(yy, xx, col + 1);
        *(float2*)&out[((size_t)(b * SQ + NCV + tt)) * DM + col] = make_float2(vx, vy);
    } else {  // EPL_GATE
        int b = row >> 8, n = row & 255;
        int p = idx[n];
        float2 hc = *(const float2*)&res[(size_t)row * DM + col];
        float2 hn = *(const float2*)&extra[((size_t)(b * SQ + n)) * DM + col];
        float g0 = 1.f / (1.f + expf(-vx));
        float g1 = 1.f / (1.f + expf(-vy));
        float2 r;
        r.x = hc.x + g0 * (hn.x - hc.x);
        r.y = hc.y + g1 * (hn.y - hc.y);
        *(float2*)&out[((size_t)b * WSQ + p) * DM + col] = r;
    }
}

template <int MODE>
__global__ void __launch_bounds__(256) mma_gemm_k(
    const __half* __restrict__ Ah, const __half* __restrict__ Bh,
    const float* __restrict__ bias, float* __restrict__ out,
    __half* __restrict__ outh,
    int M, int N, int K,
    const float* __restrict__ res, const float* __restrict__ extra,
    const int* __restrict__ idx) {
    extern __shared__ char sm[];
    const uint32_t smb = smem_u32(sm);
    const int tid = threadIdx.x;
    const int lane = tid & 31;
    const int w = tid >> 5;
    const int wm = w >> 1;
    const int wn = w & 1;
    const int m0 = blockIdx.y * 128;
    const int n0 = blockIdx.x * 128;

    float acc[2][8][4];
#pragma unroll
    for (int i = 0; i < 2; i++)
#pragma unroll
        for (int j = 0; j < 8; j++)
#pragma unroll
            for (int q = 0; q < 4; q++) acc[i][j][q] = 0.f;

    const int nkt = K >> 6;

    int crow[4], ck8[4];
    size_t asrc[4], bsrc[4];
    uint32_t coff[4];
#pragma unroll
    for (int j = 0; j < 4; j++) {
        int c = tid + 256 * j;
        crow[j] = c >> 3;
        ck8[j] = c & 7;
        coff[j] = (uint32_t)crow[j] * 128u + (uint32_t)((ck8[j] ^ (crow[j] & 7)) << 4);
        asrc[j] = (size_t)(m0 + crow[j]) * K + ck8[j] * 8;
        bsrc[j] = (size_t)(n0 + crow[j]) * K + ck8[j] * 8;
    }

#define ISSUE_STAGE(kt)                                                        \
    do {                                                                       \
        const int kk0 = (kt) << 6;                                             \
        const uint32_t sb = smb + (uint32_t)((kt) % 3) * STG_B;                \
        _Pragma("unroll") for (int j = 0; j < 4; j++) {                        \
            cp16(sb + coff[j],          Ah + asrc[j] + kk0);                   \
            cp16(sb + 16384u + coff[j], Bh + bsrc[j] + kk0);                   \
        }                                                                      \
        asm volatile("cp.async.commit_group;" ::: "memory");                   \
    } while (0)

    ISSUE_STAGE(0);
    ISSUE_STAGE(1);

    const uint32_t rowAb[2] = {
        (uint32_t)(wm * 32 + 0  + (lane & 7) + ((lane >> 3) & 1) * 8) * 128u,
        (uint32_t)(wm * 32 + 16 + (lane & 7) + ((lane >> 3) & 1) * 8) * 128u};
    const int a_k8add = lane >> 4;
    uint32_t rowBb[4];
#pragma unroll
    for (int nfp = 0; nfp < 4; nfp++)
        rowBb[nfp] = (uint32_t)(wn * 64 + nfp * 16 + ((lane >> 4) << 3) + (lane & 7)) * 128u;
    const int b_k8add = (lane >> 3) & 1;
    const uint32_t swz = (uint32_t)(lane & 7);

    for (int kt = 0; kt < nkt; kt++) {
        if (kt + 1 < nkt) {
            asm volatile("cp.async.wait_group 1;" ::: "memory");
        } else {
            asm volatile("cp.async.wait_group 0;" ::: "memory");
        }
        __syncthreads();
        if (kt + 2 < nkt) ISSUE_STAGE(kt + 2);

        const uint32_t sb = smb + (uint32_t)(kt % 3) * STG_B;
#pragma unroll
        for (int ks = 0; ks < 4; ks++) {
            uint32_t ah[2][4];
#pragma unroll
            for (int mf = 0; mf < 2; mf++) {
                uint32_t off = rowAb[mf] +
                    ((((uint32_t)(ks * 2 + a_k8add)) ^ swz) << 4);
                ldsm4(ah[mf], sb + off);
            }
#pragma unroll
            for (int nfp = 0; nfp < 4; nfp++) {
                uint32_t off = rowBb[nfp] +
                    ((((uint32_t)(ks * 2 + b_k8add)) ^ swz) << 4);
                uint32_t bh[4];
                ldsm4(bh, sb + 16384u + off);
#pragma unroll
                for (int mf = 0; mf < 2; mf++) {
                    mma16816(acc[mf][2 * nfp],     ah[mf], bh);
                    mma16816(acc[mf][2 * nfp + 1], ah[mf], bh + 2);
                }
            }
        }
    }
#undef ISSUE_STAGE

#pragma unroll
    for (int mf = 0; mf < 2; mf++) {
        int row = m0 + wm * 32 + mf * 16 + (lane >> 2);
#pragma unroll
        for (int nf = 0; nf < 8; nf++) {
            int col = n0 + wn * 64 + nf * 8 + (lane & 3) * 2;
            epi_store2<MODE>(out, outh, N, row, col,
                             acc[mf][nf][0], acc[mf][nf][1], bias, res, extra, idx);
            epi_store2<MODE>(out, outh, N, row + 8, col,
                             acc[mf][nf][2], acc[mf][nf][3], bias, res, extra, idx);
        }
    }
}

// ---------------- host launcher ----------------
extern "C" void kernel_launch(void* const* d_in, const int* in_sizes, int n_in,
                              void* d_out, int out_size) {
    const float* h_map   = (const float*)d_in[0];
    const float* frame   = (const float*)d_in[1];
    const int*   idx     = (const int*)  d_in[2];
    const float* Wqkv    = (const float*)d_in[3];
    const float* bqkv    = (const float*)d_in[4];
    const float* Wo      = (const float*)d_in[5];
    const float* bo      = (const float*)d_in[6];
    const float* ln1g    = (const float*)d_in[7];
    const float* ln1b    = (const float*)d_in[8];
    const float* W1      = (const float*)d_in[9];
    const float* b1      = (const float*)d_in[10];
    const float* W2      = (const float*)d_in[11];
    const float* b2      = (const float*)d_in[12];
    const float* ln2g    = (const float*)d_in[13];
    const float* ln2b    = (const float*)d_in[14];
    const float* nfg     = (const float*)d_in[15];
    const float* nfb     = (const float*)d_in[16];
    const float* patch_w = (const float*)d_in[17];
    const float* patch_b = (const float*)d_in[18];
    const float* gate_w  = (const float*)d_in[19];
    const float* gate_b  = (const float*)d_in[20];
    float* out = (float*)d_out;

    float *x, *ln, *hcv;
    __half *lnh, *qkvh, *ath, *h1h, *cth, *pth, *wh;
    cudaGetSymbolAddress((void**)&x, g_x);
    cudaGetSymbolAddress((void**)&ln, g_ln);
    cudaGetSymbolAddress((void**)&hcv, g_hcv);
    cudaGetSymbolAddress((void**)&lnh, g_lnh);
    cudaGetSymbolAddress((void**)&qkvh, g_qkvh);
    cudaGetSymbolAddress((void**)&ath, g_ath);
    cudaGetSymbolAddress((void**)&h1h, g_h1h);
    cudaGetSymbolAddress((void**)&cth, g_cth);
    cudaGetSymbolAddress((void**)&pth, g_pth);
    cudaGetSymbolAddress((void**)&wh, g_wh);

    cudaFuncSetAttribute(mma_gemm_k<EPL_PLAIN>,  cudaFuncAttributeMaxDynamicSharedMemorySize, GSMEM_BYTES);
    cudaFuncSetAttribute(mma_gemm_k<EPL_RES>,    cudaFuncAttributeMaxDynamicSharedMemorySize, GSMEM_BYTES);
    cudaFuncSetAttribute(mma_gemm_k<EPL_GELU>,   cudaFuncAttributeMaxDynamicSharedMemorySize, GSMEM_BYTES);
    cudaFuncSetAttribute(mma_gemm_k<EPL_IMGTOK>, cudaFuncAttributeMaxDynamicSharedMemorySize, GSMEM_BYTES);
    cudaFuncSetAttribute(mma_gemm_k<EPL_GATE>,   cudaFuncAttributeMaxDynamicSharedMemorySize, GSMEM_BYTES);
    cudaFuncSetAttribute(mma_gemm_k<EPL_QKVH>,   cudaFuncAttributeMaxDynamicSharedMemorySize, GSMEM_BYTES);
    cudaFuncSetAttribute(attn_fa_k, cudaFuncAttributeMaxDynamicSharedMemorySize, ATT_SMEM);

    // pass-through copy; gated scatter overwrites idx positions
    cudaMemcpyAsync(out, h_map, sizeof(float) * (size_t)BB * WSQ * DM,
                    cudaMemcpyDeviceToDevice, 0);

    // weight conversions (once per launch)
    wcvt_k<<<1179648 / 1024, 256>>>(Wqkv,    wh + WOFF_QKV);
    wcvt_k<<<393216  / 1024, 256>>>(Wo,      wh + WOFF_WO);
    wcvt_k<<<1572864 / 1024, 256>>>(W1,      wh + WOFF_W1);
    wcvt_k<<<1572864 / 1024, 256>>>(W2,      wh + WOFF_W2);
    wcvt_k<<<196608  / 1024, 256>>>(patch_w, wh + WOFF_PW);
    wcvt_k<<<131072  / 1024, 256>>>(gate_w,  wh + WOFF_GW);

    embed_k<<<16384, 256>>>(h_map, idx, hcv, x);
    im2col_k<<<(4096 * 768) / 256, 256>>>(frame, pth);
    mma_gemm_k<EPL_IMGTOK><<<dim3(2, 32), 256, GSMEM_BYTES>>>(
        pth, wh + WOFF_PW, patch_b, x, nullptr,
        4096, 256, 768, nullptr, nullptr, nullptr);

    const int NTOK = BB * SQ;  // 20480
    for (int l = 0; l < NDEPTH; l++) {
        ln_k<false><<<NTOK / 8, 256>>>(x, nullptr, lnh,
                                       ln1g + l * 256, ln1b + l * 256);
        mma_gemm_k<EPL_QKVH><<<dim3(6, 160), 256, GSMEM_BYTES>>>(
            lnh, wh + WOFF_QKV + (size_t)l * 196608,
            bqkv + l * 768, nullptr, qkvh,
            NTOK, 768, 256, nullptr, nullptr, nullptr);
        attn_fa_k<<<BB * NHEADS, 320, ATT_SMEM>>>(qkvh, ath);
        mma_gemm_k<EPL_RES><<<dim3(2, 160), 256, GSMEM_BYTES>>>(
            ath, wh + WOFF_WO + (size_t)l * 65536,
            bo + l * 256, x, nullptr,
            NTOK, 256, 256, x, nullptr, nullptr);
        ln_k<false><<<NTOK / 8, 256>>>(x, nullptr, lnh,
                                       ln2g + l * 256, ln2b + l * 256);
        mma_gemm_k<EPL_GELU><<<dim3(8, 160), 256, GSMEM_BYTES>>>(
            lnh, wh + WOFF_W1 + (size_t)l * 262144,
            b1 + l * 1024, nullptr, h1h,
            NTOK, 1024, 256, nullptr, nullptr, nullptr);
        mma_gemm_k<EPL_RES><<<dim3(2, 160), 256, GSMEM_BYTES>>>(
            h1h, wh + WOFF_W2 + (size_t)l * 262144,
            b2 + l * 256, x, nullptr,
            NTOK, 256, 1024, x, nullptr, nullptr);
    }

    ln_k<true><<<NTOK / 8, 256>>>(x, ln, lnh, nfg, nfb);
    cat_k<<<(16384 * 512) / 256, 256>>>(hcv, ln, cth);
    mma_gemm_k<EPL_GATE><<<dim3(2, 128), 256, GSMEM_BYTES>>>(
        cth, wh + WOFF_GW, gate_b, out, nullptr,
        16384, 256, 512, hcv, ln, idx);
}